// round 1
// baseline (speedup 1.0000x reference)
#include <cuda_runtime.h>
#include <cstdint>

#define T_SEQ 2048
#define NHEAD 16
#define HD 64
#define CDIM 1024
#define BSZ 4
#define MROWS (BSZ * T_SEQ)  // 8192

// Scratch (allocation-free rule: __device__ globals)
__device__ float g_q[(size_t)BSZ * NHEAD * T_SEQ * HD];
__device__ float g_k[(size_t)BSZ * NHEAD * T_SEQ * HD];
__device__ float g_v[(size_t)BSZ * NHEAD * T_SEQ * HD];
__device__ float g_y[(size_t)MROWS * CDIM];

__device__ __forceinline__ uint32_t f2tf(float x) {
    uint32_t y;
    asm("cvt.rna.tf32.f32 %0, %1;" : "=r"(y) : "f"(x));
    return y;
}

__device__ __forceinline__ void split_tf32(float x, float& h, float& l) {
    float hf = __uint_as_float(f2tf(x));
    h = hf;
    l = __uint_as_float(f2tf(x - hf));
}

__device__ __forceinline__ void mma8(float c[4],
                                     uint32_t a0, uint32_t a1, uint32_t a2, uint32_t a3,
                                     uint32_t b0, uint32_t b1) {
    asm("mma.sync.aligned.m16n8k8.row.col.f32.tf32.tf32.f32 "
        "{%0,%1,%2,%3}, {%4,%5,%6,%7}, {%8,%9}, {%0,%1,%2,%3};\n"
        : "+f"(c[0]), "+f"(c[1]), "+f"(c[2]), "+f"(c[3])
        : "r"(a0), "r"(a1), "r"(a2), "r"(a3), "r"(b0), "r"(b1));
}

__device__ __forceinline__ void qkv_store(int m, int n, float v0, float v1) {
    int part = n >> 10;
    int cc = n & 1023;
    int h = cc >> 6, d = cc & 63;
    int b = m >> 11, t = m & 2047;
    if (part == 0) { v0 *= 0.125f; v1 *= 0.125f; }  // fold 1/sqrt(64) into Q
    float* dst = (part == 0) ? g_q : (part == 1) ? g_k : g_v;
    size_t off = ((((size_t)b * NHEAD + h) * T_SEQ + t) << 6) + d;
    *reinterpret_cast<float2*>(dst + off) = make_float2(v0, v1);
}

// ---------------------------------------------------------------------------
// 3xTF32 GEMM: C[M,N] = A[M,K] * B[K,N] + bias. BM=128, BN=128, BK=16.
// 256 threads = 8 warps in 2x4 grid, warp tile 64x32 (4 m-tiles x 4 n-tiles).
// MODE 0: scatter epilogue into g_q/g_k/g_v.  MODE 1: direct store to out.
// ---------------------------------------------------------------------------
template <int N, int MODE>
__global__ __launch_bounds__(256, 1) void gemm_tf32(
    const float* __restrict__ A, const float* __restrict__ Bm,
    const float* __restrict__ bias, float* __restrict__ out) {
    __shared__ float Ah[128 * 20], Al[128 * 20];
    __shared__ float Bh[16 * 132], Bl[16 * 132];

    const int tid = threadIdx.x;
    const int lane = tid & 31, warp = tid >> 5;
    const int wm = (warp >> 2) * 64, wn = (warp & 3) * 32;
    const int m0 = blockIdx.x * 128, n0 = blockIdx.y * 128;

    float acc[4][4][4];
#pragma unroll
    for (int i = 0; i < 4; i++)
#pragma unroll
        for (int j = 0; j < 4; j++)
#pragma unroll
            for (int r = 0; r < 4; r++) acc[i][j][r] = 0.f;

    for (int kk = 0; kk < CDIM; kk += 16) {
        // Load A tile 128x16
#pragma unroll
        for (int p = 0; p < 2; p++) {
            int idx = tid + p * 256;
            int row = idx >> 2, c4 = (idx & 3) << 2;
            float4 v = *reinterpret_cast<const float4*>(A + (size_t)(m0 + row) * CDIM + kk + c4);
            float4 hv, lv;
            split_tf32(v.x, hv.x, lv.x);
            split_tf32(v.y, hv.y, lv.y);
            split_tf32(v.z, hv.z, lv.z);
            split_tf32(v.w, hv.w, lv.w);
            *reinterpret_cast<float4*>(&Ah[row * 20 + c4]) = hv;
            *reinterpret_cast<float4*>(&Al[row * 20 + c4]) = lv;
        }
        // Load B tile 16x128
#pragma unroll
        for (int p = 0; p < 2; p++) {
            int idx = tid + p * 256;
            int kr = idx >> 5, c4 = (idx & 31) << 2;
            float4 v = *reinterpret_cast<const float4*>(Bm + (size_t)(kk + kr) * N + n0 + c4);
            float4 hv, lv;
            split_tf32(v.x, hv.x, lv.x);
            split_tf32(v.y, hv.y, lv.y);
            split_tf32(v.z, hv.z, lv.z);
            split_tf32(v.w, hv.w, lv.w);
            *reinterpret_cast<float4*>(&Bh[kr * 132 + c4]) = hv;
            *reinterpret_cast<float4*>(&Bl[kr * 132 + c4]) = lv;
        }
        __syncthreads();

#pragma unroll
        for (int ks = 0; ks < 2; ks++) {
            const int k0 = ks * 8;
            uint32_t ah[4][4], al[4][4];
#pragma unroll
            for (int i = 0; i < 4; i++) {
                int base = (wm + i * 16 + (lane >> 2)) * 20 + k0 + (lane & 3);
                ah[i][0] = __float_as_uint(Ah[base]);
                ah[i][1] = __float_as_uint(Ah[base + 160]);
                ah[i][2] = __float_as_uint(Ah[base + 4]);
                ah[i][3] = __float_as_uint(Ah[base + 164]);
                al[i][0] = __float_as_uint(Al[base]);
                al[i][1] = __float_as_uint(Al[base + 160]);
                al[i][2] = __float_as_uint(Al[base + 4]);
                al[i][3] = __float_as_uint(Al[base + 164]);
            }
#pragma unroll
            for (int j = 0; j < 4; j++) {
                int bb = (k0 + (lane & 3)) * 132 + wn + j * 8 + (lane >> 2);
                uint32_t bh0 = __float_as_uint(Bh[bb]);
                uint32_t bh1 = __float_as_uint(Bh[bb + 528]);
                uint32_t bl0 = __float_as_uint(Bl[bb]);
                uint32_t bl1 = __float_as_uint(Bl[bb + 528]);
#pragma unroll
                for (int i = 0; i < 4; i++) {
                    mma8(acc[i][j], ah[i][0], ah[i][1], ah[i][2], ah[i][3], bh0, bh1);
                    mma8(acc[i][j], ah[i][0], ah[i][1], ah[i][2], ah[i][3], bl0, bl1);
                    mma8(acc[i][j], al[i][0], al[i][1], al[i][2], al[i][3], bh0, bh1);
                }
            }
        }
        __syncthreads();
    }

    // Epilogue
#pragma unroll
    for (int i = 0; i < 4; i++) {
        int row = m0 + wm + i * 16 + (lane >> 2);
#pragma unroll
        for (int j = 0; j < 4; j++) {
            int col = n0 + wn + j * 8 + ((lane & 3) << 1);
            float b0 = bias[col], b1 = bias[col + 1];
            float v00 = acc[i][j][0] + b0, v01 = acc[i][j][1] + b1;
            float v10 = acc[i][j][2] + b0, v11 = acc[i][j][3] + b1;
            if (MODE == 0) {
                qkv_store(row, col, v00, v01);
                qkv_store(row + 8, col, v10, v11);
            } else {
                *reinterpret_cast<float2*>(out + (size_t)row * N + col) = make_float2(v00, v01);
                *reinterpret_cast<float2*>(out + (size_t)(row + 8) * N + col) = make_float2(v10, v11);
            }
        }
    }
}

// ---------------------------------------------------------------------------
// Flash attention, causal. Q-tile 128 rows, key-tile 64, 8 warps (16 rows ea),
// hd=64. S=Q*K^T and O+=P*V via 3xTF32 mma. Q pre-scaled by 1/8 in qkv_store.
// ---------------------------------------------------------------------------
#define ATT_SMEM_FLOATS (2 * 128 * 68 + 4 * 64 * 68 + 2 * 8 * 16 * 68)

__global__ __launch_bounds__(256, 1) void attn_kernel() {
    extern __shared__ float sm[];
    float* Qh = sm;                   // [128][68]
    float* Ql = Qh + 128 * 68;
    float* Kh = Ql + 128 * 68;        // [key 64][d 68]
    float* Kl = Kh + 64 * 68;
    float* Vh = Kl + 64 * 68;         // transposed [d 64][key 68]
    float* Vl = Vh + 64 * 68;
    float* Ph = Vl + 64 * 68;         // per-warp [16][68]
    float* Pl = Ph + 8 * 16 * 68;

    const int tid = threadIdx.x, lane = tid & 31, warp = tid >> 5;
    const int bh = blockIdx.y;
    const int q0 = blockIdx.x * 128;
    const float* Qg = g_q + (size_t)bh * T_SEQ * HD;
    const float* Kg = g_k + (size_t)bh * T_SEQ * HD;
    const float* Vg = g_v + (size_t)bh * T_SEQ * HD;

    // Load Q tile 128x64 (already scaled by 1/8)
#pragma unroll
    for (int p = 0; p < 8; p++) {
        int idx = tid + p * 256;
        int row = idx >> 4, c4 = (idx & 15) << 2;
        float4 v = *reinterpret_cast<const float4*>(Qg + (size_t)(q0 + row) * HD + c4);
        float4 hv, lv;
        split_tf32(v.x, hv.x, lv.x);
        split_tf32(v.y, hv.y, lv.y);
        split_tf32(v.z, hv.z, lv.z);
        split_tf32(v.w, hv.w, lv.w);
        *reinterpret_cast<float4*>(&Qh[row * 68 + c4]) = hv;
        *reinterpret_cast<float4*>(&Ql[row * 68 + c4]) = lv;
    }

    float o[8][4];
#pragma unroll
    for (int j = 0; j < 8; j++)
#pragma unroll
        for (int r = 0; r < 4; r++) o[j][r] = 0.f;
    float mA = -1e30f, mB = -1e30f, lA = 0.f, lB = 0.f;

    const int arow = warp * 16 + (lane >> 2);
    const int rA = q0 + arow;
    const int rB = rA + 8;
    const int ntiles = (q0 >> 6) + 2;

    for (int kt = 0; kt < ntiles; kt++) {
        const int kt0 = kt << 6;
        __syncthreads();  // protect K/V/P smem reuse (also orders Q on iter 0)
        // Load K tile 64x64
#pragma unroll
        for (int p = 0; p < 4; p++) {
            int idx = tid + p * 256;
            int key = idx >> 4, c4 = (idx & 15) << 2;
            float4 v = *reinterpret_cast<const float4*>(Kg + (size_t)(kt0 + key) * HD + c4);
            float4 hv, lv;
            split_tf32(v.x, hv.x, lv.x);
            split_tf32(v.y, hv.y, lv.y);
            split_tf32(v.z, hv.z, lv.z);
            split_tf32(v.w, hv.w, lv.w);
            *reinterpret_cast<float4*>(&Kh[key * 68 + c4]) = hv;
            *reinterpret_cast<float4*>(&Kl[key * 68 + c4]) = lv;
        }
        // Load V tile transposed: Vs[d][key]
#pragma unroll
        for (int p = 0; p < 4; p++) {
            int idx = tid + p * 256;
            int key = idx >> 4, c4 = (idx & 15) << 2;
            float4 v = *reinterpret_cast<const float4*>(Vg + (size_t)(kt0 + key) * HD + c4);
            float h, l;
            split_tf32(v.x, h, l); Vh[(c4 + 0) * 68 + key] = h; Vl[(c4 + 0) * 68 + key] = l;
            split_tf32(v.y, h, l); Vh[(c4 + 1) * 68 + key] = h; Vl[(c4 + 1) * 68 + key] = l;
            split_tf32(v.z, h, l); Vh[(c4 + 2) * 68 + key] = h; Vl[(c4 + 2) * 68 + key] = l;
            split_tf32(v.w, h, l); Vh[(c4 + 3) * 68 + key] = h; Vl[(c4 + 3) * 68 + key] = l;
        }
        __syncthreads();

        // S = Q * K^T (16 x 64 per warp)
        float s[8][4];
#pragma unroll
        for (int j = 0; j < 8; j++)
#pragma unroll
            for (int r = 0; r < 4; r++) s[j][r] = 0.f;

#pragma unroll
        for (int k0 = 0; k0 < 64; k0 += 8) {
            int ab = arow * 68 + k0 + (lane & 3);
            uint32_t ah0 = __float_as_uint(Qh[ab]);
            uint32_t ah1 = __float_as_uint(Qh[ab + 8 * 68]);
            uint32_t ah2 = __float_as_uint(Qh[ab + 4]);
            uint32_t ah3 = __float_as_uint(Qh[ab + 8 * 68 + 4]);
            uint32_t al0 = __float_as_uint(Ql[ab]);
            uint32_t al1 = __float_as_uint(Ql[ab + 8 * 68]);
            uint32_t al2 = __float_as_uint(Ql[ab + 4]);
            uint32_t al3 = __float_as_uint(Ql[ab + 8 * 68 + 4]);
#pragma unroll
            for (int j = 0; j < 8; j++) {
                int bb = (j * 8 + (lane >> 2)) * 68 + k0 + (lane & 3);
                uint32_t bh0 = __float_as_uint(Kh[bb]);
                uint32_t bh1 = __float_as_uint(Kh[bb + 4]);
                uint32_t bl0 = __float_as_uint(Kl[bb]);
                uint32_t bl1 = __float_as_uint(Kl[bb + 4]);
                mma8(s[j], ah0, ah1, ah2, ah3, bh0, bh1);
                mma8(s[j], ah0, ah1, ah2, ah3, bl0, bl1);
                mma8(s[j], al0, al1, al2, al3, bh0, bh1);
            }
        }

        // Causal mask (only diagonal-band tiles need it)
        if (kt0 + 63 > q0) {
#pragma unroll
            for (int j = 0; j < 8; j++) {
                int c = kt0 + j * 8 + ((lane & 3) << 1);
                if (c > rA) s[j][0] = -1e30f;
                if (c + 1 > rA) s[j][1] = -1e30f;
                if (c > rB) s[j][2] = -1e30f;
                if (c + 1 > rB) s[j][3] = -1e30f;
            }
        }

        // Online softmax
        float tA = -1e30f, tB = -1e30f;
#pragma unroll
        for (int j = 0; j < 8; j++) {
            tA = fmaxf(tA, fmaxf(s[j][0], s[j][1]));
            tB = fmaxf(tB, fmaxf(s[j][2], s[j][3]));
        }
        tA = fmaxf(tA, __shfl_xor_sync(0xffffffffu, tA, 1));
        tA = fmaxf(tA, __shfl_xor_sync(0xffffffffu, tA, 2));
        tB = fmaxf(tB, __shfl_xor_sync(0xffffffffu, tB, 1));
        tB = fmaxf(tB, __shfl_xor_sync(0xffffffffu, tB, 2));
        float mAn = fmaxf(mA, tA), mBn = fmaxf(mB, tB);
        float aA = __expf(mA - mAn), aB = __expf(mB - mBn);
        mA = mAn; mB = mBn;
        lA *= aA; lB *= aB;

        const int pwbase = warp * 16 * 68;
#pragma unroll
        for (int j = 0; j < 8; j++) {
            float p0 = __expf(s[j][0] - mA), p1 = __expf(s[j][1] - mA);
            float p2 = __expf(s[j][2] - mB), p3 = __expf(s[j][3] - mB);
            lA += p0 + p1;
            lB += p2 + p3;
            o[j][0] *= aA; o[j][1] *= aA; o[j][2] *= aB; o[j][3] *= aB;
            int pb = pwbase + (lane >> 2) * 68 + j * 8 + ((lane & 3) << 1);
            float h0, l0, h1, l1;
            split_tf32(p0, h0, l0); split_tf32(p1, h1, l1);
            *reinterpret_cast<float2*>(&Ph[pb]) = make_float2(h0, h1);
            *reinterpret_cast<float2*>(&Pl[pb]) = make_float2(l0, l1);
            split_tf32(p2, h0, l0); split_tf32(p3, h1, l1);
            *reinterpret_cast<float2*>(&Ph[pb + 8 * 68]) = make_float2(h0, h1);
            *reinterpret_cast<float2*>(&Pl[pb + 8 * 68]) = make_float2(l0, l1);
        }
        __syncwarp();

        // O += P * V
#pragma unroll
        for (int k0 = 0; k0 < 64; k0 += 8) {
            int ab = pwbase + (lane >> 2) * 68 + k0 + (lane & 3);
            uint32_t ph0 = __float_as_uint(Ph[ab]);
            uint32_t ph1 = __float_as_uint(Ph[ab + 8 * 68]);
            uint32_t ph2 = __float_as_uint(Ph[ab + 4]);
            uint32_t ph3 = __float_as_uint(Ph[ab + 8 * 68 + 4]);
            uint32_t pl0 = __float_as_uint(Pl[ab]);
            uint32_t pl1 = __float_as_uint(Pl[ab + 8 * 68]);
            uint32_t pl2 = __float_as_uint(Pl[ab + 4]);
            uint32_t pl3 = __float_as_uint(Pl[ab + 8 * 68 + 4]);
#pragma unroll
            for (int j = 0; j < 8; j++) {
                int bb = (j * 8 + (lane >> 2)) * 68 + k0 + (lane & 3);
                uint32_t vh0 = __float_as_uint(Vh[bb]);
                uint32_t vh1 = __float_as_uint(Vh[bb + 4]);
                uint32_t vl0 = __float_as_uint(Vl[bb]);
                uint32_t vl1 = __float_as_uint(Vl[bb + 4]);
                mma8(o[j], ph0, ph1, ph2, ph3, vh0, vh1);
                mma8(o[j], ph0, ph1, ph2, ph3, vl0, vl1);
                mma8(o[j], pl0, pl1, pl2, pl3, vh0, vh1);
            }
        }
    }

    // Normalize and write out to g_y [token][C]
    lA += __shfl_xor_sync(0xffffffffu, lA, 1);
    lA += __shfl_xor_sync(0xffffffffu, lA, 2);
    lB += __shfl_xor_sync(0xffffffffu, lB, 1);
    lB += __shfl_xor_sync(0xffffffffu, lB, 2);
    float iA = 1.f / lA, iB = 1.f / lB;

    const int b = bh >> 4, h = bh & 15;
    const int tokA = b * T_SEQ + rA;  // rA = q0 + warp*16 + lane/4
#pragma unroll
    for (int j = 0; j < 8; j++) {
        int col = h * 64 + j * 8 + ((lane & 3) << 1);
        *reinterpret_cast<float2*>(g_y + (size_t)tokA * CDIM + col) =
            make_float2(o[j][0] * iA, o[j][1] * iA);
        *reinterpret_cast<float2*>(g_y + (size_t)(tokA + 8) * CDIM + col) =
            make_float2(o[j][2] * iB, o[j][3] * iB);
    }
}

extern "C" void kernel_launch(void* const* d_in, const int* in_sizes, int n_in,
                              void* d_out, int out_size) {
    const float* x    = (const float*)d_in[0];
    const float* Wqkv = (const float*)d_in[1];
    const float* bqkv = (const float*)d_in[2];
    const float* Wp   = (const float*)d_in[3];
    const float* bp   = (const float*)d_in[4];
    float* out = (float*)d_out;

    cudaFuncSetAttribute(attn_kernel, cudaFuncAttributeMaxDynamicSharedMemorySize,
                         ATT_SMEM_FLOATS * (int)sizeof(float));

    void* yp = nullptr;
    cudaGetSymbolAddress(&yp, g_y);

    dim3 blk(256);
    // 1) QKV projection, scattered into g_q/g_k/g_v (Q pre-scaled)
    gemm_tf32<3 * CDIM, 0><<<dim3(MROWS / 128, (3 * CDIM) / 128), blk>>>(x, Wqkv, bqkv, nullptr);
    // 2) Causal flash attention -> g_y
    attn_kernel<<<dim3(T_SEQ / 128, BSZ * NHEAD), blk,
                  ATT_SMEM_FLOATS * (int)sizeof(float)>>>();
    // 3) Output projection -> d_out
    gemm_tf32<CDIM, 1><<<dim3(MROWS / 128, CDIM / 128), blk>>>((const float*)yp, Wp, bp, out);
}

// round 2
// speedup vs baseline: 1.5901x; 1.5901x over previous
#include <cuda_runtime.h>
#include <cstdint>

#define T_SEQ 2048
#define NHEAD 16
#define HD 64
#define CDIM 1024
#define BSZ 4
#define MROWS (BSZ * T_SEQ)  // 8192

// Scratch (allocation-free rule: __device__ globals)
__device__ float g_q[(size_t)BSZ * NHEAD * T_SEQ * HD];
__device__ float g_k[(size_t)BSZ * NHEAD * T_SEQ * HD];
__device__ float g_v[(size_t)BSZ * NHEAD * T_SEQ * HD];
__device__ float g_y[(size_t)MROWS * CDIM];

__device__ __forceinline__ uint32_t f2tf(float x) {
    uint32_t y;
    asm("cvt.rna.tf32.f32 %0, %1;" : "=r"(y) : "f"(x));
    return y;
}
__device__ __forceinline__ float rnaf(float x) { return __uint_as_float(f2tf(x)); }

__device__ __forceinline__ void split_tf32(float x, float& h, float& l) {
    float hf = rnaf(x);
    h = hf;
    l = rnaf(x - hf);
}

__device__ __forceinline__ void split4(const float4& v, float4& h, float4& l) {
    split_tf32(v.x, h.x, l.x);
    split_tf32(v.y, h.y, l.y);
    split_tf32(v.z, h.z, l.z);
    split_tf32(v.w, h.w, l.w);
}
__device__ __forceinline__ float4 rna4(const float4& v) {
    return make_float4(rnaf(v.x), rnaf(v.y), rnaf(v.z), rnaf(v.w));
}

__device__ __forceinline__ void mma8(float c[4],
                                     uint32_t a0, uint32_t a1, uint32_t a2, uint32_t a3,
                                     uint32_t b0, uint32_t b1) {
    asm("mma.sync.aligned.m16n8k8.row.col.f32.tf32.tf32.f32 "
        "{%0,%1,%2,%3}, {%4,%5,%6,%7}, {%8,%9}, {%0,%1,%2,%3};\n"
        : "+f"(c[0]), "+f"(c[1]), "+f"(c[2]), "+f"(c[3])
        : "r"(a0), "r"(a1), "r"(a2), "r"(a3), "r"(b0), "r"(b1));
}

__device__ __forceinline__ void qkv_store(int m, int n, float v0, float v1) {
    int part = n >> 10;
    int cc = n & 1023;
    int h = cc >> 6, d = cc & 63;
    int b = m >> 11, t = m & 2047;
    if (part == 0) { v0 *= 0.125f; v1 *= 0.125f; }  // fold 1/sqrt(64) into Q
    float* dst = (part == 0) ? g_q : (part == 1) ? g_k : g_v;
    size_t off = ((((size_t)b * NHEAD + h) * T_SEQ + t) << 6) + d;
    *reinterpret_cast<float2*>(dst + off) = make_float2(v0, v1);
}

// ---------------------------------------------------------------------------
// 2xTF32 GEMM (A split h/l, B single rna): C = A[M,1024] * B[1024,N] + bias.
// BM=128, BN=128, BK=16. 256 thr = 8 warps (2x4), warp tile 64x32.
// Software pipelined: LDG prefetch regs + double-buffered smem, 1 bar/iter.
// MODE 0: scatter into g_q/g_k/g_v.  MODE 1: direct store to out.
// ---------------------------------------------------------------------------
#define GEMM_SMEM_FLOATS (2 * 128 * 20 * 2 + 2 * 16 * 132)

template <int N, int MODE>
__global__ __launch_bounds__(256, 1) void gemm_tf32(
    const float* __restrict__ A, const float* __restrict__ Bm,
    const float* __restrict__ bias, float* __restrict__ out) {
    extern __shared__ float sm[];
    float* Ah = sm;                         // [2][128*20]
    float* Al = Ah + 2 * 128 * 20;
    float* Bs = Al + 2 * 128 * 20;          // [2][16*132]

    const int tid = threadIdx.x;
    const int lane = tid & 31, warp = tid >> 5;
    const int wm = (warp >> 2) * 64, wn = (warp & 3) * 32;
    const int m0 = blockIdx.x * 128, n0 = blockIdx.y * 128;

    const int ar0 = tid >> 2, ac0 = (tid & 3) << 2;    // A rows ar0, ar0+64
    const int br0 = tid >> 5, bc0 = (tid & 31) << 2;   // B rows br0, br0+8

    float4 va0, va1, vb0, vb1;

    float acc[4][4][4];
#pragma unroll
    for (int i = 0; i < 4; i++)
#pragma unroll
        for (int j = 0; j < 4; j++)
#pragma unroll
            for (int r = 0; r < 4; r++) acc[i][j][r] = 0.f;

    // prologue: fetch + stage tile 0
    {
        const int kk = 0;
        va0 = *reinterpret_cast<const float4*>(A + (size_t)(m0 + ar0) * CDIM + kk + ac0);
        va1 = *reinterpret_cast<const float4*>(A + (size_t)(m0 + ar0 + 64) * CDIM + kk + ac0);
        vb0 = *reinterpret_cast<const float4*>(Bm + (size_t)(kk + br0) * N + n0 + bc0);
        vb1 = *reinterpret_cast<const float4*>(Bm + (size_t)(kk + br0 + 8) * N + n0 + bc0);
        float4 hv, lv;
        split4(va0, hv, lv);
        *reinterpret_cast<float4*>(&Ah[ar0 * 20 + ac0]) = hv;
        *reinterpret_cast<float4*>(&Al[ar0 * 20 + ac0]) = lv;
        split4(va1, hv, lv);
        *reinterpret_cast<float4*>(&Ah[(ar0 + 64) * 20 + ac0]) = hv;
        *reinterpret_cast<float4*>(&Al[(ar0 + 64) * 20 + ac0]) = lv;
        *reinterpret_cast<float4*>(&Bs[br0 * 132 + bc0]) = rna4(vb0);
        *reinterpret_cast<float4*>(&Bs[(br0 + 8) * 132 + bc0]) = rna4(vb1);
    }
    __syncthreads();

    const int NK = CDIM / 16;
    for (int kt = 0; kt < NK; kt++) {
        const int cur = kt & 1;
        const bool more = (kt + 1 < NK);
        if (more) {
            const int kk = (kt + 1) * 16;
            va0 = *reinterpret_cast<const float4*>(A + (size_t)(m0 + ar0) * CDIM + kk + ac0);
            va1 = *reinterpret_cast<const float4*>(A + (size_t)(m0 + ar0 + 64) * CDIM + kk + ac0);
            vb0 = *reinterpret_cast<const float4*>(Bm + (size_t)(kk + br0) * N + n0 + bc0);
            vb1 = *reinterpret_cast<const float4*>(Bm + (size_t)(kk + br0 + 8) * N + n0 + bc0);
        }

        const float* cAh = Ah + cur * 128 * 20;
        const float* cAl = Al + cur * 128 * 20;
        const float* cBs = Bs + cur * 16 * 132;
#pragma unroll
        for (int ks = 0; ks < 2; ks++) {
            const int k0 = ks * 8;
            uint32_t ah[4][4], al[4][4];
#pragma unroll
            for (int i = 0; i < 4; i++) {
                int base = (wm + i * 16 + (lane >> 2)) * 20 + k0 + (lane & 3);
                ah[i][0] = __float_as_uint(cAh[base]);
                ah[i][1] = __float_as_uint(cAh[base + 160]);
                ah[i][2] = __float_as_uint(cAh[base + 4]);
                ah[i][3] = __float_as_uint(cAh[base + 164]);
                al[i][0] = __float_as_uint(cAl[base]);
                al[i][1] = __float_as_uint(cAl[base + 160]);
                al[i][2] = __float_as_uint(cAl[base + 4]);
                al[i][3] = __float_as_uint(cAl[base + 164]);
            }
#pragma unroll
            for (int j = 0; j < 4; j++) {
                int bb = (k0 + (lane & 3)) * 132 + wn + j * 8 + (lane >> 2);
                uint32_t b0 = __float_as_uint(cBs[bb]);
                uint32_t b1 = __float_as_uint(cBs[bb + 528]);
#pragma unroll
                for (int i = 0; i < 4; i++) {
                    mma8(acc[i][j], ah[i][0], ah[i][1], ah[i][2], ah[i][3], b0, b1);
                    mma8(acc[i][j], al[i][0], al[i][1], al[i][2], al[i][3], b0, b1);
                }
            }
        }

        if (more) {
            float* nAh = Ah + (1 - cur) * 128 * 20;
            float* nAl = Al + (1 - cur) * 128 * 20;
            float* nBs = Bs + (1 - cur) * 16 * 132;
            float4 hv, lv;
            split4(va0, hv, lv);
            *reinterpret_cast<float4*>(&nAh[ar0 * 20 + ac0]) = hv;
            *reinterpret_cast<float4*>(&nAl[ar0 * 20 + ac0]) = lv;
            split4(va1, hv, lv);
            *reinterpret_cast<float4*>(&nAh[(ar0 + 64) * 20 + ac0]) = hv;
            *reinterpret_cast<float4*>(&nAl[(ar0 + 64) * 20 + ac0]) = lv;
            *reinterpret_cast<float4*>(&nBs[br0 * 132 + bc0]) = rna4(vb0);
            *reinterpret_cast<float4*>(&nBs[(br0 + 8) * 132 + bc0]) = rna4(vb1);
        }
        __syncthreads();
    }

    // Epilogue
#pragma unroll
    for (int i = 0; i < 4; i++) {
        int row = m0 + wm + i * 16 + (lane >> 2);
#pragma unroll
        for (int j = 0; j < 4; j++) {
            int col = n0 + wn + j * 8 + ((lane & 3) << 1);
            float b0 = bias[col], b1 = bias[col + 1];
            float v00 = acc[i][j][0] + b0, v01 = acc[i][j][1] + b1;
            float v10 = acc[i][j][2] + b0, v11 = acc[i][j][3] + b1;
            if (MODE == 0) {
                qkv_store(row, col, v00, v01);
                qkv_store(row + 8, col, v10, v11);
            } else {
                *reinterpret_cast<float2*>(out + (size_t)row * N + col) = make_float2(v00, v01);
                *reinterpret_cast<float2*>(out + (size_t)(row + 8) * N + col) = make_float2(v10, v11);
            }
        }
    }
}

// ---------------------------------------------------------------------------
// Flash attention, causal. Q-tile 128, key-tile 64, 8 warps (16 rows each).
// 2xTF32: Q and P split h/l; K and V single rna. K/V double-buffered +
// register-prefetched; 1 __syncthreads per key-tile.
// ---------------------------------------------------------------------------
#define ATT_SMEM_FLOATS (2 * 128 * 68 + 2 * 64 * 68 + 2 * 64 * 68 + 2 * 8 * 16 * 68)

__global__ __launch_bounds__(256, 1) void attn_kernel() {
    extern __shared__ float sm[];
    float* Qh = sm;                         // [128][68]
    float* Ql = Qh + 128 * 68;
    float* Ks = Ql + 128 * 68;              // [2][key 64][d 68]
    float* Vs = Ks + 2 * 64 * 68;           // [2][d 64][key 68] (transposed)
    float* Ph = Vs + 2 * 64 * 68;           // per-warp [16][68]
    float* Pl = Ph + 8 * 16 * 68;

    const int tid = threadIdx.x, lane = tid & 31, warp = tid >> 5;
    const int bh = blockIdx.y;
    const int q0 = blockIdx.x * 128;
    const float* Qg = g_q + (size_t)bh * T_SEQ * HD;
    const float* Kg = g_k + (size_t)bh * T_SEQ * HD;
    const float* Vg = g_v + (size_t)bh * T_SEQ * HD;

    const int kvrow = tid >> 4, kvc4 = (tid & 15) << 2;  // + p*16 rows
    float4 fk[4], fv[4];

    // prefetch K/V tile 0
#pragma unroll
    for (int p = 0; p < 4; p++) {
        fk[p] = *reinterpret_cast<const float4*>(Kg + (size_t)(kvrow + p * 16) * HD + kvc4);
        fv[p] = *reinterpret_cast<const float4*>(Vg + (size_t)(kvrow + p * 16) * HD + kvc4);
    }

    // Load Q tile 128x64 (already scaled by 1/8), split h/l
#pragma unroll
    for (int p = 0; p < 8; p++) {
        int idx = tid + p * 256;
        int row = idx >> 4, c4 = (idx & 15) << 2;
        float4 v = *reinterpret_cast<const float4*>(Qg + (size_t)(q0 + row) * HD + c4);
        float4 hv, lv;
        split4(v, hv, lv);
        *reinterpret_cast<float4*>(&Qh[row * 68 + c4]) = hv;
        *reinterpret_cast<float4*>(&Ql[row * 68 + c4]) = lv;
    }

    // stage K/V tile 0
#pragma unroll
    for (int p = 0; p < 4; p++) {
        int key = kvrow + p * 16;
        *reinterpret_cast<float4*>(&Ks[key * 68 + kvc4]) = rna4(fk[p]);
        Vs[(kvc4 + 0) * 68 + key] = rnaf(fv[p].x);
        Vs[(kvc4 + 1) * 68 + key] = rnaf(fv[p].y);
        Vs[(kvc4 + 2) * 68 + key] = rnaf(fv[p].z);
        Vs[(kvc4 + 3) * 68 + key] = rnaf(fv[p].w);
    }
    __syncthreads();

    float o[8][4];
#pragma unroll
    for (int j = 0; j < 8; j++)
#pragma unroll
        for (int r = 0; r < 4; r++) o[j][r] = 0.f;
    float mA = -1e30f, mB = -1e30f, lA = 0.f, lB = 0.f;

    const int arow = warp * 16 + (lane >> 2);
    const int rA = q0 + arow;
    const int rB = rA + 8;
    const int ntiles = (q0 >> 6) + 2;

    for (int kt = 0; kt < ntiles; kt++) {
        const int kt0 = kt << 6;
        const int cur = kt & 1;
        const bool more = (kt + 1 < ntiles);
        if (more) {
            const int nk0 = kt0 + 64;
#pragma unroll
            for (int p = 0; p < 4; p++) {
                fk[p] = *reinterpret_cast<const float4*>(Kg + (size_t)(nk0 + kvrow + p * 16) * HD + kvc4);
                fv[p] = *reinterpret_cast<const float4*>(Vg + (size_t)(nk0 + kvrow + p * 16) * HD + kvc4);
            }
        }

        const float* Kb = Ks + cur * 64 * 68;
        const float* Vb = Vs + cur * 64 * 68;

        // S = Q * K^T (16 x 64 per warp), 2 MMAs per tile-pair
        float s[8][4];
#pragma unroll
        for (int j = 0; j < 8; j++)
#pragma unroll
            for (int r = 0; r < 4; r++) s[j][r] = 0.f;

#pragma unroll
        for (int k0 = 0; k0 < 64; k0 += 8) {
            int ab = arow * 68 + k0 + (lane & 3);
            uint32_t ah0 = __float_as_uint(Qh[ab]);
            uint32_t ah1 = __float_as_uint(Qh[ab + 8 * 68]);
            uint32_t ah2 = __float_as_uint(Qh[ab + 4]);
            uint32_t ah3 = __float_as_uint(Qh[ab + 8 * 68 + 4]);
            uint32_t al0 = __float_as_uint(Ql[ab]);
            uint32_t al1 = __float_as_uint(Ql[ab + 8 * 68]);
            uint32_t al2 = __float_as_uint(Ql[ab + 4]);
            uint32_t al3 = __float_as_uint(Ql[ab + 8 * 68 + 4]);
#pragma unroll
            for (int j = 0; j < 8; j++) {
                int bb = (j * 8 + (lane >> 2)) * 68 + k0 + (lane & 3);
                uint32_t b0 = __float_as_uint(Kb[bb]);
                uint32_t b1 = __float_as_uint(Kb[bb + 4]);
                mma8(s[j], ah0, ah1, ah2, ah3, b0, b1);
                mma8(s[j], al0, al1, al2, al3, b0, b1);
            }
        }

        // Causal mask (diagonal-band tiles only)
        if (kt0 + 63 > q0) {
#pragma unroll
            for (int j = 0; j < 8; j++) {
                int c = kt0 + j * 8 + ((lane & 3) << 1);
                if (c > rA) s[j][0] = -1e30f;
                if (c + 1 > rA) s[j][1] = -1e30f;
                if (c > rB) s[j][2] = -1e30f;
                if (c + 1 > rB) s[j][3] = -1e30f;
            }
        }

        // Online softmax
        float tA = -1e30f, tB = -1e30f;
#pragma unroll
        for (int j = 0; j < 8; j++) {
            tA = fmaxf(tA, fmaxf(s[j][0], s[j][1]));
            tB = fmaxf(tB, fmaxf(s[j][2], s[j][3]));
        }
        tA = fmaxf(tA, __shfl_xor_sync(0xffffffffu, tA, 1));
        tA = fmaxf(tA, __shfl_xor_sync(0xffffffffu, tA, 2));
        tB = fmaxf(tB, __shfl_xor_sync(0xffffffffu, tB, 1));
        tB = fmaxf(tB, __shfl_xor_sync(0xffffffffu, tB, 2));
        float mAn = fmaxf(mA, tA), mBn = fmaxf(mB, tB);
        float aA = __expf(mA - mAn), aB = __expf(mB - mBn);
        mA = mAn; mB = mBn;
        lA *= aA; lB *= aB;

        const int pwbase = warp * 16 * 68;
#pragma unroll
        for (int j = 0; j < 8; j++) {
            float p0 = __expf(s[j][0] - mA), p1 = __expf(s[j][1] - mA);
            float p2 = __expf(s[j][2] - mB), p3 = __expf(s[j][3] - mB);
            lA += p0 + p1;
            lB += p2 + p3;
            o[j][0] *= aA; o[j][1] *= aA; o[j][2] *= aB; o[j][3] *= aB;
            int pb = pwbase + (lane >> 2) * 68 + j * 8 + ((lane & 3) << 1);
            float h0, l0, h1, l1;
            split_tf32(p0, h0, l0); split_tf32(p1, h1, l1);
            *reinterpret_cast<float2*>(&Ph[pb]) = make_float2(h0, h1);
            *reinterpret_cast<float2*>(&Pl[pb]) = make_float2(l0, l1);
            split_tf32(p2, h0, l0); split_tf32(p3, h1, l1);
            *reinterpret_cast<float2*>(&Ph[pb + 8 * 68]) = make_float2(h0, h1);
            *reinterpret_cast<float2*>(&Pl[pb + 8 * 68]) = make_float2(l0, l1);
        }
        __syncwarp();

        // O += P * V, 2 MMAs per tile-pair
#pragma unroll
        for (int k0 = 0; k0 < 64; k0 += 8) {
            int ab = pwbase + (lane >> 2) * 68 + k0 + (lane & 3);
            uint32_t ph0 = __float_as_uint(Ph[ab]);
            uint32_t ph1 = __float_as_uint(Ph[ab + 8 * 68]);
            uint32_t ph2 = __float_as_uint(Ph[ab + 4]);
            uint32_t ph3 = __float_as_uint(Ph[ab + 8 * 68 + 4]);
            uint32_t pl0 = __float_as_uint(Pl[ab]);
            uint32_t pl1 = __float_as_uint(Pl[ab + 8 * 68]);
            uint32_t pl2 = __float_as_uint(Pl[ab + 4]);
            uint32_t pl3 = __float_as_uint(Pl[ab + 8 * 68 + 4]);
#pragma unroll
            for (int j = 0; j < 8; j++) {
                int bb = (j * 8 + (lane >> 2)) * 68 + k0 + (lane & 3);
                uint32_t v0 = __float_as_uint(Vb[bb]);
                uint32_t v1 = __float_as_uint(Vb[bb + 4]);
                mma8(o[j], ph0, ph1, ph2, ph3, v0, v1);
                mma8(o[j], pl0, pl1, pl2, pl3, v0, v1);
            }
        }

        if (more) {
            float* nK = Ks + (1 - cur) * 64 * 68;
            float* nV = Vs + (1 - cur) * 64 * 68;
#pragma unroll
            for (int p = 0; p < 4; p++) {
                int key = kvrow + p * 16;
                *reinterpret_cast<float4*>(&nK[key * 68 + kvc4]) = rna4(fk[p]);
                nV[(kvc4 + 0) * 68 + key] = rnaf(fv[p].x);
                nV[(kvc4 + 1) * 68 + key] = rnaf(fv[p].y);
                nV[(kvc4 + 2) * 68 + key] = rnaf(fv[p].z);
                nV[(kvc4 + 3) * 68 + key] = rnaf(fv[p].w);
            }
        }
        __syncthreads();
    }

    // Normalize and write to g_y [token][C]
    lA += __shfl_xor_sync(0xffffffffu, lA, 1);
    lA += __shfl_xor_sync(0xffffffffu, lA, 2);
    lB += __shfl_xor_sync(0xffffffffu, lB, 1);
    lB += __shfl_xor_sync(0xffffffffu, lB, 2);
    float iA = 1.f / lA, iB = 1.f / lB;

    const int b = bh >> 4, h = bh & 15;
    const int tokA = b * T_SEQ + rA;
#pragma unroll
    for (int j = 0; j < 8; j++) {
        int col = h * 64 + j * 8 + ((lane & 3) << 1);
        *reinterpret_cast<float2*>(g_y + (size_t)tokA * CDIM + col) =
            make_float2(o[j][0] * iA, o[j][1] * iA);
        *reinterpret_cast<float2*>(g_y + (size_t)(tokA + 8) * CDIM + col) =
            make_float2(o[j][2] * iB, o[j][3] * iB);
    }
}

extern "C" void kernel_launch(void* const* d_in, const int* in_sizes, int n_in,
                              void* d_out, int out_size) {
    const float* x    = (const float*)d_in[0];
    const float* Wqkv = (const float*)d_in[1];
    const float* bqkv = (const float*)d_in[2];
    const float* Wp   = (const float*)d_in[3];
    const float* bp   = (const float*)d_in[4];
    float* out = (float*)d_out;

    cudaFuncSetAttribute(attn_kernel, cudaFuncAttributeMaxDynamicSharedMemorySize,
                         ATT_SMEM_FLOATS * (int)sizeof(float));
    cudaFuncSetAttribute(gemm_tf32<3 * CDIM, 0>, cudaFuncAttributeMaxDynamicSharedMemorySize,
                         GEMM_SMEM_FLOATS * (int)sizeof(float));
    cudaFuncSetAttribute(gemm_tf32<CDIM, 1>, cudaFuncAttributeMaxDynamicSharedMemorySize,
                         GEMM_SMEM_FLOATS * (int)sizeof(float));

    void* yp = nullptr;
    cudaGetSymbolAddress(&yp, g_y);

    dim3 blk(256);
    // 1) QKV projection, scattered into g_q/g_k/g_v (Q pre-scaled)
    gemm_tf32<3 * CDIM, 0><<<dim3(MROWS / 128, (3 * CDIM) / 128), blk,
                             GEMM_SMEM_FLOATS * (int)sizeof(float)>>>(x, Wqkv, bqkv, nullptr);
    // 2) Causal flash attention -> g_y
    attn_kernel<<<dim3(T_SEQ / 128, BSZ * NHEAD), blk,
                  ATT_SMEM_FLOATS * (int)sizeof(float)>>>();
    // 3) Output projection -> d_out
    gemm_tf32<CDIM, 1><<<dim3(MROWS / 128, CDIM / 128), blk,
                         GEMM_SMEM_FLOATS * (int)sizeof(float)>>>((const float*)yp, Wp, bp, out);
}

// round 4
// speedup vs baseline: 2.0340x; 1.2792x over previous
#include <cuda_runtime.h>
#include <cuda_bf16.h>
#include <cstdint>

#define T_SEQ 2048
#define NHEAD 16
#define HD 64
#define CDIM 1024
#define BSZ 4
#define MROWS 8192

// ---------------- device scratch (allocation-free rule) ----------------
__device__ float g_q[(size_t)BSZ * NHEAD * T_SEQ * HD];
__device__ float g_k[(size_t)BSZ * NHEAD * T_SEQ * HD];
__device__ float g_v[(size_t)BSZ * NHEAD * T_SEQ * HD];
__device__ __nv_bfloat16 g_xh[(size_t)MROWS * CDIM], g_xl[(size_t)MROWS * CDIM];
__device__ __nv_bfloat16 g_wh[(size_t)3 * CDIM * CDIM], g_wl[(size_t)3 * CDIM * CDIM];
__device__ __nv_bfloat16 g_wph[(size_t)CDIM * CDIM], g_wpl[(size_t)CDIM * CDIM];
__device__ __nv_bfloat16 g_yh[(size_t)MROWS * CDIM], g_yl[(size_t)MROWS * CDIM];

// ---------------- numeric helpers ----------------
__device__ __forceinline__ void bsplit(float x, __nv_bfloat16& h, __nv_bfloat16& l) {
    h = __float2bfloat16_rn(x);
    l = __float2bfloat16_rn(x - __bfloat162float(h));
}
// two floats -> packed bf16x2 high part + packed bf16x2 low part
__device__ __forceinline__ void bsplit2(float x, float y, uint32_t& hp, uint32_t& lp) {
    __nv_bfloat162 hb = __floats2bfloat162_rn(x, y);
    float hx = __bfloat162float(__low2bfloat16(hb));
    float hy = __bfloat162float(__high2bfloat16(hb));
    __nv_bfloat162 lb = __floats2bfloat162_rn(x - hx, y - hy);
    hp = *reinterpret_cast<uint32_t*>(&hb);
    lp = *reinterpret_cast<uint32_t*>(&lb);
}

__device__ __forceinline__ void mma16(float c[4],
                                      uint32_t a0, uint32_t a1, uint32_t a2, uint32_t a3,
                                      uint32_t b0, uint32_t b1) {
    asm("mma.sync.aligned.m16n8k16.row.col.f32.bf16.bf16.f32 "
        "{%0,%1,%2,%3}, {%4,%5,%6,%7}, {%8,%9}, {%0,%1,%2,%3};\n"
        : "+f"(c[0]), "+f"(c[1]), "+f"(c[2]), "+f"(c[3])
        : "r"(a0), "r"(a1), "r"(a2), "r"(a3), "r"(b0), "r"(b1));
}

__device__ __forceinline__ void qkv_store(int m, int n, float v0, float v1) {
    int part = n >> 10;
    int cc = n & 1023;
    int h = cc >> 6, d = cc & 63;
    int b = m >> 11, t = m & 2047;
    if (part == 0) { v0 *= 0.125f; v1 *= 0.125f; }  // fold 1/sqrt(64) into Q
    float* dst = (part == 0) ? g_q : (part == 1) ? g_k : g_v;
    size_t off = ((((size_t)b * NHEAD + h) * T_SEQ + t) << 6) + d;
    *reinterpret_cast<float2*>(dst + off) = make_float2(v0, v1);
}

// ---------------- pre-kernels: split / transpose+split ----------------
__global__ void xsplit_kernel(const float* __restrict__ X, __nv_bfloat16* __restrict__ Xh,
                              __nv_bfloat16* __restrict__ Xl) {
    int i = blockIdx.x * blockDim.x + threadIdx.x;  // float4 index
    float4 v = reinterpret_cast<const float4*>(X)[i];
    uint32_t h01, l01, h23, l23;
    bsplit2(v.x, v.y, h01, l01);
    bsplit2(v.z, v.w, h23, l23);
    reinterpret_cast<uint2*>(Xh)[i] = make_uint2(h01, h23);
    reinterpret_cast<uint2*>(Xl)[i] = make_uint2(l01, l23);
}

// W [1024, N] fp32 -> Wh/Wl [N, 1024] bf16 (transpose + split)
__global__ void wsplit_kernel(const float* __restrict__ W, __nv_bfloat16* __restrict__ Wh,
                              __nv_bfloat16* __restrict__ Wl, int N) {
    __shared__ float tile[32][33];
    const int nb = blockIdx.x * 32, kb = blockIdx.y * 32;
    const int tx = threadIdx.x, ty = threadIdx.y;
#pragma unroll
    for (int r = 0; r < 32; r += 8)
        tile[ty + r][tx] = W[(size_t)(kb + ty + r) * N + nb + tx];
    __syncthreads();
#pragma unroll
    for (int r = 0; r < 32; r += 8) {
        float v = tile[tx][ty + r];  // = W[kb+tx][nb+ty+r]
        __nv_bfloat16 h, l;
        bsplit(v, h, l);
        size_t o = (size_t)(nb + ty + r) * CDIM + kb + tx;
        Wh[o] = h;
        Wl[o] = l;
    }
}

// ---------------------------------------------------------------------------
// bf16 3-term GEMM: C[M,NTOT] = A[M,1024] @ B^T + bias.
// A pre-split bf16 [M,1024] (h,l); B pre-split+transposed bf16 [NTOT,1024].
// 512 threads = 16 warps (4x4), CTA tile 128x128, warp tile 32x32, BK=32,
// double-buffered smem, reg prefetch, 1 barrier/stage.
// Rows padded to 40 bf16 (20 words): conflict-free 32-bit fragment reads.
// MODE 0: scatter into g_q/g_k/g_v (Q scaled 1/8).  MODE 1: direct store.
// ---------------------------------------------------------------------------
#define GEMM_SMEM_BYTES (2 * 4 * 128 * 40 * 2)  // 81920

template <int NTOT, int MODE>
__global__ __launch_bounds__(512, 1) void gemm_bf16(
    const __nv_bfloat16* __restrict__ Ah_g, const __nv_bfloat16* __restrict__ Al_g,
    const __nv_bfloat16* __restrict__ Bh_g, const __nv_bfloat16* __restrict__ Bl_g,
    const float* __restrict__ bias, float* __restrict__ out) {
    extern __shared__ char smem[];
    const int tid = threadIdx.x, lane = tid & 31, warp = tid >> 5;
    const int wm = (warp >> 2) * 32, wn = (warp & 3) * 32;
    const int m0 = blockIdx.x * 128, n0 = blockIdx.y * 128;
    const int kp = lane & 3, r4 = lane >> 2;

    const int lr = tid >> 2;           // 0..127 (row within tile)
    const int lc = (tid & 3) * 8;      // bf16 col group within BK=32
    const uint32_t sbyte = (uint32_t)lr * 80 + (uint32_t)(tid & 3) * 16;

    const __nv_bfloat16* pAh = Ah_g + (size_t)(m0 + lr) * CDIM + lc;
    const __nv_bfloat16* pAl = Al_g + (size_t)(m0 + lr) * CDIM + lc;
    const __nv_bfloat16* pBh = Bh_g + (size_t)(n0 + lr) * CDIM + lc;
    const __nv_bfloat16* pBl = Bl_g + (size_t)(n0 + lr) * CDIM + lc;

    float acc[2][4][4];
#pragma unroll
    for (int i = 0; i < 2; i++)
#pragma unroll
        for (int j = 0; j < 4; j++)
#pragma unroll
            for (int r = 0; r < 4; r++) acc[i][j][r] = 0.f;

    uint4 va, vb, vc, vd;
    // prologue: fetch + stage tile 0
    va = *reinterpret_cast<const uint4*>(pAh);
    vb = *reinterpret_cast<const uint4*>(pAl);
    vc = *reinterpret_cast<const uint4*>(pBh);
    vd = *reinterpret_cast<const uint4*>(pBl);
    *reinterpret_cast<uint4*>(smem + sbyte) = va;
    *reinterpret_cast<uint4*>(smem + 10240 + sbyte) = vb;
    *reinterpret_cast<uint4*>(smem + 20480 + sbyte) = vc;
    *reinterpret_cast<uint4*>(smem + 30720 + sbyte) = vd;
    __syncthreads();

    const int NK = CDIM / 32;  // 32 stages
    for (int kt = 0; kt < NK; kt++) {
        const int buf = kt & 1;
        const bool more = (kt + 1 < NK);
        if (more) {
            const int kk = (kt + 1) * 32;
            va = *reinterpret_cast<const uint4*>(pAh + kk);
            vb = *reinterpret_cast<const uint4*>(pAl + kk);
            vc = *reinterpret_cast<const uint4*>(pBh + kk);
            vd = *reinterpret_cast<const uint4*>(pBl + kk);
        }

        const char* base = smem + buf * 40960;
        const uint32_t* sAh = reinterpret_cast<const uint32_t*>(base);
        const uint32_t* sAl = reinterpret_cast<const uint32_t*>(base + 10240);
        const uint32_t* sBh = reinterpret_cast<const uint32_t*>(base + 20480);
        const uint32_t* sBl = reinterpret_cast<const uint32_t*>(base + 30720);

#pragma unroll
        for (int ks = 0; ks < 2; ks++) {
            const int k0 = ks * 8;  // word offset of this k16 step
            uint32_t ah[2][4], al[2][4];
#pragma unroll
            for (int i = 0; i < 2; i++) {
                int w = (wm + i * 16 + r4) * 20 + kp + k0;
                ah[i][0] = sAh[w];       ah[i][1] = sAh[w + 160];
                ah[i][2] = sAh[w + 4];   ah[i][3] = sAh[w + 164];
                al[i][0] = sAl[w];       al[i][1] = sAl[w + 160];
                al[i][2] = sAl[w + 4];   al[i][3] = sAl[w + 164];
            }
#pragma unroll
            for (int j = 0; j < 4; j++) {
                int w = (wn + j * 8 + r4) * 20 + kp + k0;
                uint32_t bh0 = sBh[w], bh1 = sBh[w + 4];
                uint32_t bl0 = sBl[w], bl1 = sBl[w + 4];
#pragma unroll
                for (int i = 0; i < 2; i++) {
                    mma16(acc[i][j], ah[i][0], ah[i][1], ah[i][2], ah[i][3], bh0, bh1);
                    mma16(acc[i][j], ah[i][0], ah[i][1], ah[i][2], ah[i][3], bl0, bl1);
                    mma16(acc[i][j], al[i][0], al[i][1], al[i][2], al[i][3], bh0, bh1);
                }
            }
        }

        if (more) {
            char* nb2 = smem + (1 - buf) * 40960;
            *reinterpret_cast<uint4*>(nb2 + sbyte) = va;
            *reinterpret_cast<uint4*>(nb2 + 10240 + sbyte) = vb;
            *reinterpret_cast<uint4*>(nb2 + 20480 + sbyte) = vc;
            *reinterpret_cast<uint4*>(nb2 + 30720 + sbyte) = vd;
        }
        __syncthreads();
    }

    // Epilogue
#pragma unroll
    for (int i = 0; i < 2; i++) {
        int row = m0 + wm + i * 16 + r4;
#pragma unroll
        for (int j = 0; j < 4; j++) {
            int col = n0 + wn + j * 8 + kp * 2;
            float b0 = bias[col], b1 = bias[col + 1];
            float v00 = acc[i][j][0] + b0, v01 = acc[i][j][1] + b1;
            float v10 = acc[i][j][2] + b0, v11 = acc[i][j][3] + b1;
            if (MODE == 0) {
                qkv_store(row, col, v00, v01);
                qkv_store(row + 8, col, v10, v11);
            } else {
                *reinterpret_cast<float2*>(out + (size_t)row * NTOT + col) = make_float2(v00, v01);
                *reinterpret_cast<float2*>(out + (size_t)(row + 8) * NTOT + col) = make_float2(v10, v11);
            }
        }
    }
}

// ---------------------------------------------------------------------------
// Flash attention, causal, bf16 3-term (m16n8k16). Q-tile 128, key-tile 64,
// 8 warps x 16 q-rows. Q/K/V/P split h/l in-kernel. Rows padded to 72 bf16
// (36 words). K/V double-buffered + reg prefetch; 1 barrier per key tile.
// Epilogue writes pre-split bf16 Y (g_yh/g_yl) for the projection GEMM.
// ---------------------------------------------------------------------------
#define ASW 36  // words per padded row (72 bf16)
#define ATT_SMEM_BYTES (8 * 9216 * 2)  // 147456

__global__ __launch_bounds__(256, 1) void attn_kernel() {
    extern __shared__ __nv_bfloat16 sb[];
    __nv_bfloat16* Qh = sb;                    // [128][72]
    __nv_bfloat16* Ql = sb + 9216;
    __nv_bfloat16* Ksh = sb + 18432;           // [2][64][72]
    __nv_bfloat16* Ksl = sb + 27648;
    __nv_bfloat16* Vsh = sb + 36864;           // [2][d 64][key 72] transposed
    __nv_bfloat16* Vsl = sb + 46080;
    __nv_bfloat16* Pwh = sb + 55296;           // [8 warps][16][72]
    __nv_bfloat16* Pwl = sb + 64512;

    const int tid = threadIdx.x, lane = tid & 31, warp = tid >> 5;
    const int kp = lane & 3, r4 = lane >> 2;
    const int bh = blockIdx.y;
    const int q0 = blockIdx.x * 128;
    const float* Qg = g_q + (size_t)bh * T_SEQ * HD;
    const float* Kg = g_k + (size_t)bh * T_SEQ * HD;
    const float* Vg = g_v + (size_t)bh * T_SEQ * HD;

    const int kvrow = tid >> 4, kvc4 = (tid & 15) << 2;
    float4 fk[4], fv[4];
#pragma unroll
    for (int p = 0; p < 4; p++) {
        fk[p] = *reinterpret_cast<const float4*>(Kg + (size_t)(kvrow + p * 16) * HD + kvc4);
        fv[p] = *reinterpret_cast<const float4*>(Vg + (size_t)(kvrow + p * 16) * HD + kvc4);
    }
    // Q tile 128x64 (pre-scaled by 1/8), split h/l
#pragma unroll
    for (int p = 0; p < 8; p++) {
        int idx = tid + p * 256;
        int row = idx >> 4, c4 = (idx & 15) << 2;
        float4 v = *reinterpret_cast<const float4*>(Qg + (size_t)(q0 + row) * HD + c4);
        uint32_t h01, l01, h23, l23;
        bsplit2(v.x, v.y, h01, l01);
        bsplit2(v.z, v.w, h23, l23);
        *reinterpret_cast<uint2*>(&Qh[row * 72 + c4]) = make_uint2(h01, h23);
        *reinterpret_cast<uint2*>(&Ql[row * 72 + c4]) = make_uint2(l01, l23);
    }
    // stage K/V tile 0
#pragma unroll
    for (int p = 0; p < 4; p++) {
        int key = kvrow + p * 16;
        uint32_t h01, l01, h23, l23;
        bsplit2(fk[p].x, fk[p].y, h01, l01);
        bsplit2(fk[p].z, fk[p].w, h23, l23);
        *reinterpret_cast<uint2*>(&Ksh[key * 72 + kvc4]) = make_uint2(h01, h23);
        *reinterpret_cast<uint2*>(&Ksl[key * 72 + kvc4]) = make_uint2(l01, l23);
        __nv_bfloat16 h, l;
        bsplit(fv[p].x, h, l); Vsh[(kvc4 + 0) * 72 + key] = h; Vsl[(kvc4 + 0) * 72 + key] = l;
        bsplit(fv[p].y, h, l); Vsh[(kvc4 + 1) * 72 + key] = h; Vsl[(kvc4 + 1) * 72 + key] = l;
        bsplit(fv[p].z, h, l); Vsh[(kvc4 + 2) * 72 + key] = h; Vsl[(kvc4 + 2) * 72 + key] = l;
        bsplit(fv[p].w, h, l); Vsh[(kvc4 + 3) * 72 + key] = h; Vsl[(kvc4 + 3) * 72 + key] = l;
    }
    __syncthreads();

    float o[8][4];
#pragma unroll
    for (int j = 0; j < 8; j++)
#pragma unroll
        for (int r = 0; r < 4; r++) o[j][r] = 0.f;
    float mA = -1e30f, mB = -1e30f, lA = 0.f, lB = 0.f;

    const int arow = warp * 16 + r4;
    const int rA = q0 + arow;
    const int rB = rA + 8;
    const int ntiles = (q0 >> 6) + 2;

    const uint32_t* QhW = reinterpret_cast<const uint32_t*>(Qh);
    const uint32_t* QlW = reinterpret_cast<const uint32_t*>(Ql);
    uint32_t* PhW = reinterpret_cast<uint32_t*>(Pwh + warp * 1152);
    uint32_t* PlW = reinterpret_cast<uint32_t*>(Pwl + warp * 1152);

    for (int kt = 0; kt < ntiles; kt++) {
        const int kt0 = kt << 6;
        const int cur = kt & 1;
        const bool more = (kt + 1 < ntiles);
        if (more) {
            const int nk0 = kt0 + 64;
#pragma unroll
            for (int p = 0; p < 4; p++) {
                fk[p] = *reinterpret_cast<const float4*>(Kg + (size_t)(nk0 + kvrow + p * 16) * HD + kvc4);
                fv[p] = *reinterpret_cast<const float4*>(Vg + (size_t)(nk0 + kvrow + p * 16) * HD + kvc4);
            }
        }
        const uint32_t* KbH = reinterpret_cast<const uint32_t*>(Ksh + cur * 4608);
        const uint32_t* KbL = reinterpret_cast<const uint32_t*>(Ksl + cur * 4608);
        const uint32_t* VbH = reinterpret_cast<const uint32_t*>(Vsh + cur * 4608);
        const uint32_t* VbL = reinterpret_cast<const uint32_t*>(Vsl + cur * 4608);

        // S = Q * K^T
        float s[8][4];
#pragma unroll
        for (int j = 0; j < 8; j++)
#pragma unroll
            for (int r = 0; r < 4; r++) s[j][r] = 0.f;

#pragma unroll
        for (int ks = 0; ks < 4; ks++) {
            const int k0 = ks * 8;
            const int aw = arow * ASW + kp + k0;
            uint32_t ah0 = QhW[aw],       ah1 = QhW[aw + 8 * ASW];
            uint32_t ah2 = QhW[aw + 4],   ah3 = QhW[aw + 8 * ASW + 4];
            uint32_t al0 = QlW[aw],       al1 = QlW[aw + 8 * ASW];
            uint32_t al2 = QlW[aw + 4],   al3 = QlW[aw + 8 * ASW + 4];
#pragma unroll
            for (int j = 0; j < 8; j++) {
                const int bw = (j * 8 + r4) * ASW + kp + k0;
                uint32_t bh0 = KbH[bw], bh1 = KbH[bw + 4];
                uint32_t bl0 = KbL[bw], bl1 = KbL[bw + 4];
                mma16(s[j], ah0, ah1, ah2, ah3, bh0, bh1);
                mma16(s[j], ah0, ah1, ah2, ah3, bl0, bl1);
                mma16(s[j], al0, al1, al2, al3, bh0, bh1);
            }
        }

        // Causal mask (diagonal-band tiles only)
        if (kt0 + 63 > q0) {
#pragma unroll
            for (int j = 0; j < 8; j++) {
                int c = kt0 + j * 8 + kp * 2;
                if (c > rA) s[j][0] = -1e30f;
                if (c + 1 > rA) s[j][1] = -1e30f;
                if (c > rB) s[j][2] = -1e30f;
                if (c + 1 > rB) s[j][3] = -1e30f;
            }
        }

        // Online softmax
        float tA = -1e30f, tB = -1e30f;
#pragma unroll
        for (int j = 0; j < 8; j++) {
            tA = fmaxf(tA, fmaxf(s[j][0], s[j][1]));
            tB = fmaxf(tB, fmaxf(s[j][2], s[j][3]));
        }
        tA = fmaxf(tA, __shfl_xor_sync(0xffffffffu, tA, 1));
        tA = fmaxf(tA, __shfl_xor_sync(0xffffffffu, tA, 2));
        tB = fmaxf(tB, __shfl_xor_sync(0xffffffffu, tB, 1));
        tB = fmaxf(tB, __shfl_xor_sync(0xffffffffu, tB, 2));
        float mAn = fmaxf(mA, tA), mBn = fmaxf(mB, tB);
        float aA = __expf(mA - mAn), aB = __expf(mB - mBn);
        mA = mAn; mB = mBn;
        lA *= aA; lB *= aB;

#pragma unroll
        for (int j = 0; j < 8; j++) {
            float p0 = __expf(s[j][0] - mA), p1 = __expf(s[j][1] - mA);
            float p2 = __expf(s[j][2] - mB), p3 = __expf(s[j][3] - mB);
            lA += p0 + p1;
            lB += p2 + p3;
            o[j][0] *= aA; o[j][1] *= aA; o[j][2] *= aB; o[j][3] *= aB;
            uint32_t hp, lp;
            const int pw = r4 * ASW + j * 4 + kp;
            bsplit2(p0, p1, hp, lp);
            PhW[pw] = hp;
            PlW[pw] = lp;
            bsplit2(p2, p3, hp, lp);
            PhW[pw + 8 * ASW] = hp;
            PlW[pw + 8 * ASW] = lp;
        }
        __syncwarp();

        // O += P * V
#pragma unroll
        for (int ks = 0; ks < 4; ks++) {
            const int k0 = ks * 8;
            const int aw = r4 * ASW + kp + k0;
            uint32_t ph0 = PhW[aw],       ph1 = PhW[aw + 8 * ASW];
            uint32_t ph2 = PhW[aw + 4],   ph3 = PhW[aw + 8 * ASW + 4];
            uint32_t pl0 = PlW[aw],       pl1 = PlW[aw + 8 * ASW];
            uint32_t pl2 = PlW[aw + 4],   pl3 = PlW[aw + 8 * ASW + 4];
#pragma unroll
            for (int j = 0; j < 8; j++) {
                const int bw = (j * 8 + r4) * ASW + kp + k0;
                uint32_t vh0 = VbH[bw], vh1 = VbH[bw + 4];
                uint32_t vl0 = VbL[bw], vl1 = VbL[bw + 4];
                mma16(o[j], ph0, ph1, ph2, ph3, vh0, vh1);
                mma16(o[j], ph0, ph1, ph2, ph3, vl0, vl1);
                mma16(o[j], pl0, pl1, pl2, pl3, vh0, vh1);
            }
        }

        if (more) {
            __nv_bfloat16* nKh = Ksh + (1 - cur) * 4608;
            __nv_bfloat16* nKl = Ksl + (1 - cur) * 4608;
            __nv_bfloat16* nVh = Vsh + (1 - cur) * 4608;
            __nv_bfloat16* nVl = Vsl + (1 - cur) * 4608;
#pragma unroll
            for (int p = 0; p < 4; p++) {
                int key = kvrow + p * 16;
                uint32_t h01, l01, h23, l23;
                bsplit2(fk[p].x, fk[p].y, h01, l01);
                bsplit2(fk[p].z, fk[p].w, h23, l23);
                *reinterpret_cast<uint2*>(&nKh[key * 72 + kvc4]) = make_uint2(h01, h23);
                *reinterpret_cast<uint2*>(&nKl[key * 72 + kvc4]) = make_uint2(l01, l23);
                __nv_bfloat16 h, l;
                bsplit(fv[p].x, h, l); nVh[(kvc4 + 0) * 72 + key] = h; nVl[(kvc4 + 0) * 72 + key] = l;
                bsplit(fv[p].y, h, l); nVh[(kvc4 + 1) * 72 + key] = h; nVl[(kvc4 + 1) * 72 + key] = l;
                bsplit(fv[p].z, h, l); nVh[(kvc4 + 2) * 72 + key] = h; nVl[(kvc4 + 2) * 72 + key] = l;
                bsplit(fv[p].w, h, l); nVh[(kvc4 + 3) * 72 + key] = h; nVl[(kvc4 + 3) * 72 + key] = l;
            }
        }
        __syncthreads();
    }

    // Normalize and write pre-split bf16 Y
    lA += __shfl_xor_sync(0xffffffffu, lA, 1);
    lA += __shfl_xor_sync(0xffffffffu, lA, 2);
    lB += __shfl_xor_sync(0xffffffffu, lB, 1);
    lB += __shfl_xor_sync(0xffffffffu, lB, 2);
    float iA = 1.f / lA, iB = 1.f / lB;

    const int b = bh >> 4, h = bh & 15;
    const int tokA = b * T_SEQ + rA;
#pragma unroll
    for (int j = 0; j < 8; j++) {
        int col = h * 64 + j * 8 + kp * 2;
        size_t oA = (size_t)tokA * CDIM + col;
        size_t oB = (size_t)(tokA + 8) * CDIM + col;
        uint32_t hp, lp;
        bsplit2(o[j][0] * iA, o[j][1] * iA, hp, lp);
        *reinterpret_cast<uint32_t*>(g_yh + oA) = hp;
        *reinterpret_cast<uint32_t*>(g_yl + oA) = lp;
        bsplit2(o[j][2] * iB, o[j][3] * iB, hp, lp);
        *reinterpret_cast<uint32_t*>(g_yh + oB) = hp;
        *reinterpret_cast<uint32_t*>(g_yl + oB) = lp;
    }
}

// ---------------- launch ----------------
extern "C" void kernel_launch(void* const* d_in, const int* in_sizes, int n_in,
                              void* d_out, int out_size) {
    const float* x    = (const float*)d_in[0];
    const float* Wqkv = (const float*)d_in[1];
    const float* bqkv = (const float*)d_in[2];
    const float* Wp   = (const float*)d_in[3];
    const float* bp   = (const float*)d_in[4];
    float* out = (float*)d_out;

    void *xh, *xl, *wh, *wl, *wph, *wpl, *yh, *yl;
    cudaGetSymbolAddress(&xh, g_xh);   cudaGetSymbolAddress(&xl, g_xl);
    cudaGetSymbolAddress(&wh, g_wh);   cudaGetSymbolAddress(&wl, g_wl);
    cudaGetSymbolAddress(&wph, g_wph); cudaGetSymbolAddress(&wpl, g_wpl);
    cudaGetSymbolAddress(&yh, g_yh);   cudaGetSymbolAddress(&yl, g_yl);

    cudaFuncSetAttribute(attn_kernel, cudaFuncAttributeMaxDynamicSharedMemorySize,
                         ATT_SMEM_BYTES);
    cudaFuncSetAttribute(gemm_bf16<3 * CDIM, 0>, cudaFuncAttributeMaxDynamicSharedMemorySize,
                         GEMM_SMEM_BYTES);
    cudaFuncSetAttribute(gemm_bf16<CDIM, 1>, cudaFuncAttributeMaxDynamicSharedMemorySize,
                         GEMM_SMEM_BYTES);

    // 0) pre-split inputs/weights
    xsplit_kernel<<<(MROWS * CDIM / 4) / 256, 256>>>(x, (__nv_bfloat16*)xh, (__nv_bfloat16*)xl);
    wsplit_kernel<<<dim3(3 * CDIM / 32, CDIM / 32), dim3(32, 8)>>>(
        Wqkv, (__nv_bfloat16*)wh, (__nv_bfloat16*)wl, 3 * CDIM);
    wsplit_kernel<<<dim3(CDIM / 32, CDIM / 32), dim3(32, 8)>>>(
        Wp, (__nv_bfloat16*)wph, (__nv_bfloat16*)wpl, CDIM);

    // 1) QKV projection -> g_q/g_k/g_v
    gemm_bf16<3 * CDIM, 0><<<dim3(MROWS / 128, 3 * CDIM / 128), 512, GEMM_SMEM_BYTES>>>(
        (const __nv_bfloat16*)xh, (const __nv_bfloat16*)xl,
        (const __nv_bfloat16*)wh, (const __nv_bfloat16*)wl, bqkv, nullptr);

    // 2) causal flash attention -> g_yh/g_yl (pre-split)
    attn_kernel<<<dim3(T_SEQ / 128, BSZ * NHEAD), 256, ATT_SMEM_BYTES>>>();

    // 3) output projection -> d_out
    gemm_bf16<CDIM, 1><<<dim3(MROWS / 128, CDIM / 128), 512, GEMM_SMEM_BYTES>>>(
        (const __nv_bfloat16*)yh, (const __nv_bfloat16*)yl,
        (const __nv_bfloat16*)wph, (const __nv_bfloat16*)wpl, bp, out);
}

// round 5
// speedup vs baseline: 2.1559x; 1.0599x over previous
#include <cuda_runtime.h>
#include <cuda_bf16.h>
#include <cstdint>

#define T_SEQ 2048
#define NHEAD 16
#define HD 64
#define CDIM 1024
#define BSZ 4
#define MROWS 8192

// ---------------- device scratch (allocation-free rule) ----------------
__device__ float g_q[(size_t)BSZ * NHEAD * T_SEQ * HD];
__device__ float g_k[(size_t)BSZ * NHEAD * T_SEQ * HD];
__device__ float g_v[(size_t)BSZ * NHEAD * T_SEQ * HD];
__device__ __nv_bfloat16 g_xh[(size_t)MROWS * CDIM], g_xl[(size_t)MROWS * CDIM];
__device__ __nv_bfloat16 g_wh[(size_t)3 * CDIM * CDIM], g_wl[(size_t)3 * CDIM * CDIM];
__device__ __nv_bfloat16 g_wph[(size_t)CDIM * CDIM], g_wpl[(size_t)CDIM * CDIM];
__device__ __nv_bfloat16 g_yh[(size_t)MROWS * CDIM], g_yl[(size_t)MROWS * CDIM];

// ---------------- helpers ----------------
__device__ __forceinline__ uint32_t smem_to_u32(const void* p) {
    uint32_t a;
    asm("{ .reg .u64 t; cvta.to.shared.u64 t, %1; cvt.u32.u64 %0, t; }" : "=r"(a) : "l"(p));
    return a;
}

#define LDSM4(r, addr) \
    asm volatile("ldmatrix.sync.aligned.m8n8.x4.shared.b16 {%0,%1,%2,%3}, [%4];" \
                 : "=r"((r)[0]), "=r"((r)[1]), "=r"((r)[2]), "=r"((r)[3]) : "r"(addr))

__device__ __forceinline__ void bsplit(float x, __nv_bfloat16& h, __nv_bfloat16& l) {
    h = __float2bfloat16_rn(x);
    l = __float2bfloat16_rn(x - __bfloat162float(h));
}
__device__ __forceinline__ void bsplit2(float x, float y, uint32_t& hp, uint32_t& lp) {
    __nv_bfloat162 hb = __floats2bfloat162_rn(x, y);
    float hx = __bfloat162float(__low2bfloat16(hb));
    float hy = __bfloat162float(__high2bfloat16(hb));
    __nv_bfloat162 lb = __floats2bfloat162_rn(x - hx, y - hy);
    hp = *reinterpret_cast<uint32_t*>(&hb);
    lp = *reinterpret_cast<uint32_t*>(&lb);
}

__device__ __forceinline__ void mma16(float c[4],
                                      uint32_t a0, uint32_t a1, uint32_t a2, uint32_t a3,
                                      uint32_t b0, uint32_t b1) {
    asm("mma.sync.aligned.m16n8k16.row.col.f32.bf16.bf16.f32 "
        "{%0,%1,%2,%3}, {%4,%5,%6,%7}, {%8,%9}, {%0,%1,%2,%3};\n"
        : "+f"(c[0]), "+f"(c[1]), "+f"(c[2]), "+f"(c[3])
        : "r"(a0), "r"(a1), "r"(a2), "r"(a3), "r"(b0), "r"(b1));
}

__device__ __forceinline__ void qkv_store(int m, int n, float v0, float v1) {
    int part = n >> 10;
    int cc = n & 1023;
    int h = cc >> 6, d = cc & 63;
    int b = m >> 11, t = m & 2047;
    if (part == 0) { v0 *= 0.125f; v1 *= 0.125f; }  // fold 1/sqrt(64) into Q
    float* dst = (part == 0) ? g_q : (part == 1) ? g_k : g_v;
    size_t off = ((((size_t)b * NHEAD + h) * T_SEQ + t) << 6) + d;
    *reinterpret_cast<float2*>(dst + off) = make_float2(v0, v1);
}

// ---------------- pre-kernels ----------------
__global__ void xsplit_kernel(const float* __restrict__ X, __nv_bfloat16* __restrict__ Xh,
                              __nv_bfloat16* __restrict__ Xl) {
    int i = blockIdx.x * blockDim.x + threadIdx.x;
    float4 v = reinterpret_cast<const float4*>(X)[i];
    uint32_t h01, l01, h23, l23;
    bsplit2(v.x, v.y, h01, l01);
    bsplit2(v.z, v.w, h23, l23);
    reinterpret_cast<uint2*>(Xh)[i] = make_uint2(h01, h23);
    reinterpret_cast<uint2*>(Xl)[i] = make_uint2(l01, l23);
}

__global__ void wsplit_kernel(const float* __restrict__ W, __nv_bfloat16* __restrict__ Wh,
                              __nv_bfloat16* __restrict__ Wl, int N) {
    __shared__ float tile[32][33];
    const int nb = blockIdx.x * 32, kb = blockIdx.y * 32;
    const int tx = threadIdx.x, ty = threadIdx.y;
#pragma unroll
    for (int r = 0; r < 32; r += 8)
        tile[ty + r][tx] = W[(size_t)(kb + ty + r) * N + nb + tx];
    __syncthreads();
#pragma unroll
    for (int r = 0; r < 32; r += 8) {
        float v = tile[tx][ty + r];
        __nv_bfloat16 h, l;
        bsplit(v, h, l);
        size_t o = (size_t)(nb + ty + r) * CDIM + kb + tx;
        Wh[o] = h;
        Wl[o] = l;
    }
}

// ---------------------------------------------------------------------------
// bf16 3-term GEMM, ldmatrix fragments. CTA 128x128, 16 warps 32x32, BK=32.
// ---------------------------------------------------------------------------
#define GEMM_SMEM_BYTES (2 * 4 * 128 * 40 * 2)  // 81920

template <int NTOT, int MODE>
__global__ __launch_bounds__(512, 1) void gemm_bf16(
    const __nv_bfloat16* __restrict__ Ah_g, const __nv_bfloat16* __restrict__ Al_g,
    const __nv_bfloat16* __restrict__ Bh_g, const __nv_bfloat16* __restrict__ Bl_g,
    const float* __restrict__ bias, float* __restrict__ out) {
    extern __shared__ char smem[];
    const uint32_t sb_u = smem_to_u32(smem);
    const int tid = threadIdx.x, lane = tid & 31, warp = tid >> 5;
    const int wm = (warp >> 2) * 32, wn = (warp & 3) * 32;
    const int m0 = blockIdx.x * 128, n0 = blockIdx.y * 128;
    const int kp = lane & 3, r4 = lane >> 2;
    const int l16 = lane & 15, lhi = lane >> 4;

    // ldmatrix per-thread address bases (relative to buffer array base)
    const uint32_t a_fa = (uint32_t)(wm + l16) * 80 + lhi * 16;
    const uint32_t b_fa = (uint32_t)(wn + l16) * 80 + lhi * 16;

    const int lr = tid >> 2;
    const int lc = (tid & 3) * 8;
    const uint32_t sbyte = (uint32_t)lr * 80 + (uint32_t)(tid & 3) * 16;

    const __nv_bfloat16* pAh = Ah_g + (size_t)(m0 + lr) * CDIM + lc;
    const __nv_bfloat16* pAl = Al_g + (size_t)(m0 + lr) * CDIM + lc;
    const __nv_bfloat16* pBh = Bh_g + (size_t)(n0 + lr) * CDIM + lc;
    const __nv_bfloat16* pBl = Bl_g + (size_t)(n0 + lr) * CDIM + lc;

    float acc[2][4][4];
#pragma unroll
    for (int i = 0; i < 2; i++)
#pragma unroll
        for (int j = 0; j < 4; j++)
#pragma unroll
            for (int r = 0; r < 4; r++) acc[i][j][r] = 0.f;

    uint4 va, vb, vc, vd;
    va = *reinterpret_cast<const uint4*>(pAh);
    vb = *reinterpret_cast<const uint4*>(pAl);
    vc = *reinterpret_cast<const uint4*>(pBh);
    vd = *reinterpret_cast<const uint4*>(pBl);
    *reinterpret_cast<uint4*>(smem + sbyte) = va;
    *reinterpret_cast<uint4*>(smem + 10240 + sbyte) = vb;
    *reinterpret_cast<uint4*>(smem + 20480 + sbyte) = vc;
    *reinterpret_cast<uint4*>(smem + 30720 + sbyte) = vd;
    __syncthreads();

    const int NK = CDIM / 32;
    for (int kt = 0; kt < NK; kt++) {
        const int buf = kt & 1;
        const bool more = (kt + 1 < NK);
        if (more) {
            const int kk = (kt + 1) * 32;
            va = *reinterpret_cast<const uint4*>(pAh + kk);
            vb = *reinterpret_cast<const uint4*>(pAl + kk);
            vc = *reinterpret_cast<const uint4*>(pBh + kk);
            vd = *reinterpret_cast<const uint4*>(pBl + kk);
        }

        const uint32_t base_u = sb_u + buf * 40960;
#pragma unroll
        for (int ks = 0; ks < 2; ks++) {
            const uint32_t ko = ks * 32;
            uint32_t ah[2][4], al[2][4], bh[2][4], bl[2][4];
#pragma unroll
            for (int i = 0; i < 2; i++) {
                LDSM4(ah[i], base_u + a_fa + i * 1280 + ko);
                LDSM4(al[i], base_u + 10240 + a_fa + i * 1280 + ko);
            }
#pragma unroll
            for (int jp = 0; jp < 2; jp++) {
                LDSM4(bh[jp], base_u + 20480 + b_fa + jp * 1280 + ko);
                LDSM4(bl[jp], base_u + 30720 + b_fa + jp * 1280 + ko);
            }
#pragma unroll
            for (int j = 0; j < 4; j++) {
                const int jp = j >> 1, sel = j & 1;
                uint32_t b0h = bh[jp][sel], b1h = bh[jp][2 + sel];
                uint32_t b0l = bl[jp][sel], b1l = bl[jp][2 + sel];
#pragma unroll
                for (int i = 0; i < 2; i++) {
                    mma16(acc[i][j], ah[i][0], ah[i][1], ah[i][2], ah[i][3], b0h, b1h);
                    mma16(acc[i][j], ah[i][0], ah[i][1], ah[i][2], ah[i][3], b0l, b1l);
                    mma16(acc[i][j], al[i][0], al[i][1], al[i][2], al[i][3], b0h, b1h);
                }
            }
        }

        if (more) {
            char* nb2 = smem + (1 - buf) * 40960;
            *reinterpret_cast<uint4*>(nb2 + sbyte) = va;
            *reinterpret_cast<uint4*>(nb2 + 10240 + sbyte) = vb;
            *reinterpret_cast<uint4*>(nb2 + 20480 + sbyte) = vc;
            *reinterpret_cast<uint4*>(nb2 + 30720 + sbyte) = vd;
        }
        __syncthreads();
    }

    // Epilogue
#pragma unroll
    for (int i = 0; i < 2; i++) {
        int row = m0 + wm + i * 16 + r4;
#pragma unroll
        for (int j = 0; j < 4; j++) {
            int col = n0 + wn + j * 8 + kp * 2;
            float b0 = bias[col], b1 = bias[col + 1];
            float v00 = acc[i][j][0] + b0, v01 = acc[i][j][1] + b1;
            float v10 = acc[i][j][2] + b0, v11 = acc[i][j][3] + b1;
            if (MODE == 0) {
                qkv_store(row, col, v00, v01);
                qkv_store(row + 8, col, v10, v11);
            } else {
                *reinterpret_cast<float2*>(out + (size_t)row * NTOT + col) = make_float2(v00, v01);
                *reinterpret_cast<float2*>(out + (size_t)(row + 8) * NTOT + col) = make_float2(v10, v11);
            }
        }
    }
}

// ---------------------------------------------------------------------------
// Flash attention, causal, bf16 3-term, ldmatrix fragments, P in registers.
// Q-tile 128, key-tile 64, 8 warps x 16 q-rows. Rows padded to 72 bf16.
// ---------------------------------------------------------------------------
#define ATT_SMEM_BYTES 110592  // (9216*2 + 4608*4*2) bf16 * 2B

__global__ __launch_bounds__(256, 1) void attn_kernel() {
    extern __shared__ __nv_bfloat16 sb[];
    __nv_bfloat16* Qh = sb;                    // [128][72]
    __nv_bfloat16* Ql = sb + 9216;
    __nv_bfloat16* Ksh = sb + 18432;           // [2][64][72]
    __nv_bfloat16* Ksl = sb + 27648;
    __nv_bfloat16* Vsh = sb + 36864;           // [2][d 64][key 72] transposed
    __nv_bfloat16* Vsl = sb + 46080;
    const uint32_t sb_u = smem_to_u32(sb);

    const int tid = threadIdx.x, lane = tid & 31, warp = tid >> 5;
    const int kp = lane & 3, r4 = lane >> 2;
    const int l16 = lane & 15, lhi = lane >> 4;
    const int bh_idx = blockIdx.y;
    const int q0 = blockIdx.x * 128;
    const float* Qg = g_q + (size_t)bh_idx * T_SEQ * HD;
    const float* Kg = g_k + (size_t)bh_idx * T_SEQ * HD;
    const float* Vg = g_v + (size_t)bh_idx * T_SEQ * HD;

    // ldmatrix address bases (bytes)
    const uint32_t qaddrH = sb_u + (uint32_t)(warp * 16 + l16) * 144 + lhi * 16;
    const uint32_t qaddrL = qaddrH + 18432;
    const uint32_t kbaseH = sb_u + 36864 + (uint32_t)l16 * 144 + lhi * 16;
    const uint32_t kbaseL = kbaseH + 18432;
    const uint32_t vbaseH = sb_u + 73728 + (uint32_t)l16 * 144 + lhi * 16;
    const uint32_t vbaseL = vbaseH + 18432;

    const int kvrow = tid >> 4, kvc4 = (tid & 15) << 2;
    float4 fk[4], fv[4];
#pragma unroll
    for (int p = 0; p < 4; p++) {
        fk[p] = *reinterpret_cast<const float4*>(Kg + (size_t)(kvrow + p * 16) * HD + kvc4);
        fv[p] = *reinterpret_cast<const float4*>(Vg + (size_t)(kvrow + p * 16) * HD + kvc4);
    }
    // Q tile 128x64 (pre-scaled by 1/8), split h/l
#pragma unroll
    for (int p = 0; p < 8; p++) {
        int idx = tid + p * 256;
        int row = idx >> 4, c4 = (idx & 15) << 2;
        float4 v = *reinterpret_cast<const float4*>(Qg + (size_t)(q0 + row) * HD + c4);
        uint32_t h01, l01, h23, l23;
        bsplit2(v.x, v.y, h01, l01);
        bsplit2(v.z, v.w, h23, l23);
        *reinterpret_cast<uint2*>(&Qh[row * 72 + c4]) = make_uint2(h01, h23);
        *reinterpret_cast<uint2*>(&Ql[row * 72 + c4]) = make_uint2(l01, l23);
    }
    // stage K/V tile 0
#pragma unroll
    for (int p = 0; p < 4; p++) {
        int key = kvrow + p * 16;
        uint32_t h01, l01, h23, l23;
        bsplit2(fk[p].x, fk[p].y, h01, l01);
        bsplit2(fk[p].z, fk[p].w, h23, l23);
        *reinterpret_cast<uint2*>(&Ksh[key * 72 + kvc4]) = make_uint2(h01, h23);
        *reinterpret_cast<uint2*>(&Ksl[key * 72 + kvc4]) = make_uint2(l01, l23);
        __nv_bfloat16 h, l;
        bsplit(fv[p].x, h, l); Vsh[(kvc4 + 0) * 72 + key] = h; Vsl[(kvc4 + 0) * 72 + key] = l;
        bsplit(fv[p].y, h, l); Vsh[(kvc4 + 1) * 72 + key] = h; Vsl[(kvc4 + 1) * 72 + key] = l;
        bsplit(fv[p].z, h, l); Vsh[(kvc4 + 2) * 72 + key] = h; Vsl[(kvc4 + 2) * 72 + key] = l;
        bsplit(fv[p].w, h, l); Vsh[(kvc4 + 3) * 72 + key] = h; Vsl[(kvc4 + 3) * 72 + key] = l;
    }
    __syncthreads();

    float o[8][4];
#pragma unroll
    for (int j = 0; j < 8; j++)
#pragma unroll
        for (int r = 0; r < 4; r++) o[j][r] = 0.f;
    float mA = -1e30f, mB = -1e30f, lA = 0.f, lB = 0.f;

    const int rA = q0 + warp * 16 + r4;
    const int rB = rA + 8;
    const int ntiles = (q0 >> 6) + 2;

    for (int kt = 0; kt < ntiles; kt++) {
        const int kt0 = kt << 6;
        const int cur = kt & 1;
        const bool more = (kt + 1 < ntiles);
        if (more) {
            const int nk0 = kt0 + 64;
#pragma unroll
            for (int p = 0; p < 4; p++) {
                fk[p] = *reinterpret_cast<const float4*>(Kg + (size_t)(nk0 + kvrow + p * 16) * HD + kvc4);
                fv[p] = *reinterpret_cast<const float4*>(Vg + (size_t)(nk0 + kvrow + p * 16) * HD + kvc4);
            }
        }
        const uint32_t kbufH = kbaseH + cur * 9216;
        const uint32_t kbufL = kbaseL + cur * 9216;
        const uint32_t vbufH = vbaseH + cur * 9216;
        const uint32_t vbufL = vbaseL + cur * 9216;

        // S = Q * K^T
        float s[8][4];
#pragma unroll
        for (int j = 0; j < 8; j++)
#pragma unroll
            for (int r = 0; r < 4; r++) s[j][r] = 0.f;

#pragma unroll
        for (int ks = 0; ks < 4; ks++) {
            const uint32_t ko = ks * 32;
            uint32_t qh[4], ql[4], kh[4][4], kl[4][4];
            LDSM4(qh, qaddrH + ko);
            LDSM4(ql, qaddrL + ko);
#pragma unroll
            for (int jp = 0; jp < 4; jp++) {
                LDSM4(kh[jp], kbufH + jp * 2304 + ko);
                LDSM4(kl[jp], kbufL + jp * 2304 + ko);
            }
#pragma unroll
            for (int j = 0; j < 8; j++) {
                const int jp = j >> 1, sel = j & 1;
                uint32_t b0h = kh[jp][sel], b1h = kh[jp][2 + sel];
                uint32_t b0l = kl[jp][sel], b1l = kl[jp][2 + sel];
                mma16(s[j], qh[0], qh[1], qh[2], qh[3], b0h, b1h);
                mma16(s[j], qh[0], qh[1], qh[2], qh[3], b0l, b1l);
                mma16(s[j], ql[0], ql[1], ql[2], ql[3], b0h, b1h);
            }
        }

        // Causal mask (diagonal-band tiles only)
        if (kt0 + 63 > q0) {
#pragma unroll
            for (int j = 0; j < 8; j++) {
                int c = kt0 + j * 8 + kp * 2;
                if (c > rA) s[j][0] = -1e30f;
                if (c + 1 > rA) s[j][1] = -1e30f;
                if (c > rB) s[j][2] = -1e30f;
                if (c + 1 > rB) s[j][3] = -1e30f;
            }
        }

        // Online softmax
        float tA = -1e30f, tB = -1e30f;
#pragma unroll
        for (int j = 0; j < 8; j++) {
            tA = fmaxf(tA, fmaxf(s[j][0], s[j][1]));
            tB = fmaxf(tB, fmaxf(s[j][2], s[j][3]));
        }
        tA = fmaxf(tA, __shfl_xor_sync(0xffffffffu, tA, 1));
        tA = fmaxf(tA, __shfl_xor_sync(0xffffffffu, tA, 2));
        tB = fmaxf(tB, __shfl_xor_sync(0xffffffffu, tB, 1));
        tB = fmaxf(tB, __shfl_xor_sync(0xffffffffu, tB, 2));
        float mAn = fmaxf(mA, tA), mBn = fmaxf(mB, tB);
        float aA = __expf(mA - mAn), aB = __expf(mB - mBn);
        mA = mAn; mB = mBn;
        lA *= aA; lB *= aB;

        // P in registers: C-fragment layout == A-fragment layout
        uint32_t ph01[8], ph23[8], pl01[8], pl23[8];
#pragma unroll
        for (int j = 0; j < 8; j++) {
            float p0 = __expf(s[j][0] - mA), p1 = __expf(s[j][1] - mA);
            float p2 = __expf(s[j][2] - mB), p3 = __expf(s[j][3] - mB);
            lA += p0 + p1;
            lB += p2 + p3;
            o[j][0] *= aA; o[j][1] *= aA; o[j][2] *= aB; o[j][3] *= aB;
            bsplit2(p0, p1, ph01[j], pl01[j]);
            bsplit2(p2, p3, ph23[j], pl23[j]);
        }

        // O += P * V
#pragma unroll
        for (int ks = 0; ks < 4; ks++) {
            const uint32_t ko = ks * 32;
            uint32_t ah0 = ph01[2 * ks],     ah1 = ph23[2 * ks];
            uint32_t ah2 = ph01[2 * ks + 1], ah3 = ph23[2 * ks + 1];
            uint32_t al0 = pl01[2 * ks],     al1 = pl23[2 * ks];
            uint32_t al2 = pl01[2 * ks + 1], al3 = pl23[2 * ks + 1];
            uint32_t vh[4][4], vl[4][4];
#pragma unroll
            for (int jp = 0; jp < 4; jp++) {
                LDSM4(vh[jp], vbufH + jp * 2304 + ko);
                LDSM4(vl[jp], vbufL + jp * 2304 + ko);
            }
#pragma unroll
            for (int j = 0; j < 8; j++) {
                const int jp = j >> 1, sel = j & 1;
                uint32_t v0h = vh[jp][sel], v1h = vh[jp][2 + sel];
                uint32_t v0l = vl[jp][sel], v1l = vl[jp][2 + sel];
                mma16(o[j], ah0, ah1, ah2, ah3, v0h, v1h);
                mma16(o[j], ah0, ah1, ah2, ah3, v0l, v1l);
                mma16(o[j], al0, al1, al2, al3, v0h, v1h);
            }
        }

        if (more) {
            __nv_bfloat16* nKh = Ksh + (1 - cur) * 4608;
            __nv_bfloat16* nKl = Ksl + (1 - cur) * 4608;
            __nv_bfloat16* nVh = Vsh + (1 - cur) * 4608;
            __nv_bfloat16* nVl = Vsl + (1 - cur) * 4608;
#pragma unroll
            for (int p = 0; p < 4; p++) {
                int key = kvrow + p * 16;
                uint32_t h01, l01, h23, l23;
                bsplit2(fk[p].x, fk[p].y, h01, l01);
                bsplit2(fk[p].z, fk[p].w, h23, l23);
                *reinterpret_cast<uint2*>(&nKh[key * 72 + kvc4]) = make_uint2(h01, h23);
                *reinterpret_cast<uint2*>(&nKl[key * 72 + kvc4]) = make_uint2(l01, l23);
                __nv_bfloat16 h, l;
                bsplit(fv[p].x, h, l); nVh[(kvc4 + 0) * 72 + key] = h; nVl[(kvc4 + 0) * 72 + key] = l;
                bsplit(fv[p].y, h, l); nVh[(kvc4 + 1) * 72 + key] = h; nVl[(kvc4 + 1) * 72 + key] = l;
                bsplit(fv[p].z, h, l); nVh[(kvc4 + 2) * 72 + key] = h; nVl[(kvc4 + 2) * 72 + key] = l;
                bsplit(fv[p].w, h, l); nVh[(kvc4 + 3) * 72 + key] = h; nVl[(kvc4 + 3) * 72 + key] = l;
            }
        }
        __syncthreads();
    }

    // Normalize and write pre-split bf16 Y
    lA += __shfl_xor_sync(0xffffffffu, lA, 1);
    lA += __shfl_xor_sync(0xffffffffu, lA, 2);
    lB += __shfl_xor_sync(0xffffffffu, lB, 1);
    lB += __shfl_xor_sync(0xffffffffu, lB, 2);
    float iA = 1.f / lA, iB = 1.f / lB;

    const int b = bh_idx >> 4, h = bh_idx & 15;
    const int tokA = b * T_SEQ + rA;
#pragma unroll
    for (int j = 0; j < 8; j++) {
        int col = h * 64 + j * 8 + kp * 2;
        size_t oA = (size_t)tokA * CDIM + col;
        size_t oB = (size_t)(tokA + 8) * CDIM + col;
        uint32_t hp, lp;
        bsplit2(o[j][0] * iA, o[j][1] * iA, hp, lp);
        *reinterpret_cast<uint32_t*>(g_yh + oA) = hp;
        *reinterpret_cast<uint32_t*>(g_yl + oA) = lp;
        bsplit2(o[j][2] * iB, o[j][3] * iB, hp, lp);
        *reinterpret_cast<uint32_t*>(g_yh + oB) = hp;
        *reinterpret_cast<uint32_t*>(g_yl + oB) = lp;
    }
}

// ---------------- launch ----------------
extern "C" void kernel_launch(void* const* d_in, const int* in_sizes, int n_in,
                              void* d_out, int out_size) {
    const float* x    = (const float*)d_in[0];
    const float* Wqkv = (const float*)d_in[1];
    const float* bqkv = (const float*)d_in[2];
    const float* Wp   = (const float*)d_in[3];
    const float* bp   = (const float*)d_in[4];
    float* out = (float*)d_out;

    void *xh, *xl, *wh, *wl, *wph, *wpl, *yh, *yl;
    cudaGetSymbolAddress(&xh, g_xh);   cudaGetSymbolAddress(&xl, g_xl);
    cudaGetSymbolAddress(&wh, g_wh);   cudaGetSymbolAddress(&wl, g_wl);
    cudaGetSymbolAddress(&wph, g_wph); cudaGetSymbolAddress(&wpl, g_wpl);
    cudaGetSymbolAddress(&yh, g_yh);   cudaGetSymbolAddress(&yl, g_yl);

    cudaFuncSetAttribute(attn_kernel, cudaFuncAttributeMaxDynamicSharedMemorySize,
                         ATT_SMEM_BYTES);
    cudaFuncSetAttribute(gemm_bf16<3 * CDIM, 0>, cudaFuncAttributeMaxDynamicSharedMemorySize,
                         GEMM_SMEM_BYTES);
    cudaFuncSetAttribute(gemm_bf16<CDIM, 1>, cudaFuncAttributeMaxDynamicSharedMemorySize,
                         GEMM_SMEM_BYTES);

    // 0) pre-split inputs/weights
    xsplit_kernel<<<(MROWS * CDIM / 4) / 256, 256>>>(x, (__nv_bfloat16*)xh, (__nv_bfloat16*)xl);
    wsplit_kernel<<<dim3(3 * CDIM / 32, CDIM / 32), dim3(32, 8)>>>(
        Wqkv, (__nv_bfloat16*)wh, (__nv_bfloat16*)wl, 3 * CDIM);
    wsplit_kernel<<<dim3(CDIM / 32, CDIM / 32), dim3(32, 8)>>>(
        Wp, (__nv_bfloat16*)wph, (__nv_bfloat16*)wpl, CDIM);

    // 1) QKV projection -> g_q/g_k/g_v
    gemm_bf16<3 * CDIM, 0><<<dim3(MROWS / 128, 3 * CDIM / 128), 512, GEMM_SMEM_BYTES>>>(
        (const __nv_bfloat16*)xh, (const __nv_bfloat16*)xl,
        (const __nv_bfloat16*)wh, (const __nv_bfloat16*)wl, bqkv, nullptr);

    // 2) causal flash attention -> g_yh/g_yl (pre-split)
    attn_kernel<<<dim3(T_SEQ / 128, BSZ * NHEAD), 256, ATT_SMEM_BYTES>>>();

    // 3) output projection -> d_out
    gemm_bf16<CDIM, 1><<<dim3(MROWS / 128, CDIM / 128), 512, GEMM_SMEM_BYTES>>>(
        (const __nv_bfloat16*)yh, (const __nv_bfloat16*)yl,
        (const __nv_bfloat16*)wph, (const __nv_bfloat16*)wpl, bp, out);
}

// round 6
// speedup vs baseline: 2.2115x; 1.0258x over previous
#include <cuda_runtime.h>
#include <cuda_bf16.h>
#include <cstdint>

#define T_SEQ 2048
#define NHEAD 16
#define HD 64
#define CDIM 1024
#define BSZ 4
#define MROWS 8192

// ---------------- device scratch (allocation-free rule) ----------------
#define QKV_ELEMS ((size_t)BSZ * NHEAD * T_SEQ * HD)
__device__ __align__(128) __nv_bfloat16 g_qh[QKV_ELEMS], g_ql[QKV_ELEMS];
__device__ __align__(128) __nv_bfloat16 g_kh[QKV_ELEMS], g_kl[QKV_ELEMS];
__device__ __align__(128) __nv_bfloat16 g_vh[QKV_ELEMS], g_vl[QKV_ELEMS];
__device__ __align__(128) __nv_bfloat16 g_xh[(size_t)MROWS * CDIM], g_xl[(size_t)MROWS * CDIM];
__device__ __align__(128) __nv_bfloat16 g_wh[(size_t)3 * CDIM * CDIM], g_wl[(size_t)3 * CDIM * CDIM];
__device__ __align__(128) __nv_bfloat16 g_wph[(size_t)CDIM * CDIM], g_wpl[(size_t)CDIM * CDIM];
__device__ __align__(128) __nv_bfloat16 g_yh[(size_t)MROWS * CDIM], g_yl[(size_t)MROWS * CDIM];

// ---------------- helpers ----------------
__device__ __forceinline__ uint32_t smem_to_u32(const void* p) {
    uint32_t a;
    asm("{ .reg .u64 t; cvta.to.shared.u64 t, %1; cvt.u32.u64 %0, t; }" : "=r"(a) : "l"(p));
    return a;
}

#define LDSM4(r, addr) \
    asm volatile("ldmatrix.sync.aligned.m8n8.x4.shared.b16 {%0,%1,%2,%3}, [%4];" \
                 : "=r"((r)[0]), "=r"((r)[1]), "=r"((r)[2]), "=r"((r)[3]) : "r"(addr))
#define LDSM4T(r, addr) \
    asm volatile("ldmatrix.sync.aligned.m8n8.x4.trans.shared.b16 {%0,%1,%2,%3}, [%4];" \
                 : "=r"((r)[0]), "=r"((r)[1]), "=r"((r)[2]), "=r"((r)[3]) : "r"(addr))
#define CP16(dst, src) \
    asm volatile("cp.async.cg.shared.global [%0], [%1], 16;" :: "r"(dst), "l"(src))
#define CP_COMMIT() asm volatile("cp.async.commit_group;" ::: "memory")
#define CP_WAIT(n) asm volatile("cp.async.wait_group %0;" :: "n"(n) : "memory")

__device__ __forceinline__ void bsplit(float x, __nv_bfloat16& h, __nv_bfloat16& l) {
    h = __float2bfloat16_rn(x);
    l = __float2bfloat16_rn(x - __bfloat162float(h));
}
__device__ __forceinline__ void bsplit2(float x, float y, uint32_t& hp, uint32_t& lp) {
    __nv_bfloat162 hb = __floats2bfloat162_rn(x, y);
    float hx = __bfloat162float(__low2bfloat16(hb));
    float hy = __bfloat162float(__high2bfloat16(hb));
    __nv_bfloat162 lb = __floats2bfloat162_rn(x - hx, y - hy);
    hp = *reinterpret_cast<uint32_t*>(&hb);
    lp = *reinterpret_cast<uint32_t*>(&lb);
}

__device__ __forceinline__ void mma16(float c[4],
                                      uint32_t a0, uint32_t a1, uint32_t a2, uint32_t a3,
                                      uint32_t b0, uint32_t b1) {
    asm("mma.sync.aligned.m16n8k16.row.col.f32.bf16.bf16.f32 "
        "{%0,%1,%2,%3}, {%4,%5,%6,%7}, {%8,%9}, {%0,%1,%2,%3};\n"
        : "+f"(c[0]), "+f"(c[1]), "+f"(c[2]), "+f"(c[3])
        : "r"(a0), "r"(a1), "r"(a2), "r"(a3), "r"(b0), "r"(b1));
}

// QKV epilogue: write pre-split bf16 h/l, Q scaled by 1/8
__device__ __forceinline__ void qkv_store_bf(int m, int n, float v0, float v1) {
    int part = n >> 10;
    int cc = n & 1023;
    int h = cc >> 6, d = cc & 63;
    int b = m >> 11, t = m & 2047;
    if (part == 0) { v0 *= 0.125f; v1 *= 0.125f; }
    __nv_bfloat16* dh = (part == 0) ? g_qh : (part == 1) ? g_kh : g_vh;
    __nv_bfloat16* dl = (part == 0) ? g_ql : (part == 1) ? g_kl : g_vl;
    size_t off = ((((size_t)b * NHEAD + h) * T_SEQ + t) << 6) + d;
    uint32_t hp, lp;
    bsplit2(v0, v1, hp, lp);
    *reinterpret_cast<uint32_t*>(dh + off) = hp;
    *reinterpret_cast<uint32_t*>(dl + off) = lp;
}

// ---------------- pre-kernels ----------------
__global__ void xsplit_kernel(const float* __restrict__ X, __nv_bfloat16* __restrict__ Xh,
                              __nv_bfloat16* __restrict__ Xl) {
    int i = blockIdx.x * blockDim.x + threadIdx.x;
    float4 v = reinterpret_cast<const float4*>(X)[i];
    uint32_t h01, l01, h23, l23;
    bsplit2(v.x, v.y, h01, l01);
    bsplit2(v.z, v.w, h23, l23);
    reinterpret_cast<uint2*>(Xh)[i] = make_uint2(h01, h23);
    reinterpret_cast<uint2*>(Xl)[i] = make_uint2(l01, l23);
}

__global__ void wsplit_kernel(const float* __restrict__ W, __nv_bfloat16* __restrict__ Wh,
                              __nv_bfloat16* __restrict__ Wl, int N) {
    __shared__ float tile[32][33];
    const int nb = blockIdx.x * 32, kb = blockIdx.y * 32;
    const int tx = threadIdx.x, ty = threadIdx.y;
#pragma unroll
    for (int r = 0; r < 32; r += 8)
        tile[ty + r][tx] = W[(size_t)(kb + ty + r) * N + nb + tx];
    __syncthreads();
#pragma unroll
    for (int r = 0; r < 32; r += 8) {
        float v = tile[tx][ty + r];
        __nv_bfloat16 h, l;
        bsplit(v, h, l);
        size_t o = (size_t)(nb + ty + r) * CDIM + kb + tx;
        Wh[o] = h;
        Wl[o] = l;
    }
}

// ---------------------------------------------------------------------------
// bf16 3-term GEMM with cp.async 4-stage pipeline. CTA 128x128, 16 warps
// 32x32, BK=32. Rows padded to 40 bf16 (80B). LDSM fragments.
// ---------------------------------------------------------------------------
#define GEMM_SMEM_BYTES (4 * 40960)  // 163840

template <int NTOT, int MODE>
__global__ __launch_bounds__(512, 1) void gemm_bf16(
    const __nv_bfloat16* __restrict__ Ah_g, const __nv_bfloat16* __restrict__ Al_g,
    const __nv_bfloat16* __restrict__ Bh_g, const __nv_bfloat16* __restrict__ Bl_g,
    const float* __restrict__ bias, float* __restrict__ out) {
    extern __shared__ char smem[];
    const uint32_t sb_u = smem_to_u32(smem);
    const int tid = threadIdx.x, lane = tid & 31, warp = tid >> 5;
    const int wm = (warp >> 2) * 32, wn = (warp & 3) * 32;
    const int m0 = blockIdx.x * 128, n0 = blockIdx.y * 128;
    const int kp = lane & 3, r4 = lane >> 2;
    const int l16 = lane & 15, lhi = lane >> 4;

    const uint32_t a_fa = (uint32_t)(wm + l16) * 80 + lhi * 16;
    const uint32_t b_fa = (uint32_t)(wn + l16) * 80 + lhi * 16;

    const int lr = tid >> 2, ch = tid & 3;
    const uint32_t soff = (uint32_t)lr * 80 + (uint32_t)ch * 16;
    const __nv_bfloat16* srcAh = Ah_g + (size_t)(m0 + lr) * CDIM + ch * 8;
    const __nv_bfloat16* srcAl = Al_g + (size_t)(m0 + lr) * CDIM + ch * 8;
    const __nv_bfloat16* srcBh = Bh_g + (size_t)(n0 + lr) * CDIM + ch * 8;
    const __nv_bfloat16* srcBl = Bl_g + (size_t)(n0 + lr) * CDIM + ch * 8;

    float acc[2][4][4];
#pragma unroll
    for (int i = 0; i < 2; i++)
#pragma unroll
        for (int j = 0; j < 4; j++)
#pragma unroll
            for (int r = 0; r < 4; r++) acc[i][j][r] = 0.f;

    const int NK = CDIM / 32;  // 32 stages

    // prologue: issue 3 stages
#pragma unroll
    for (int s = 0; s < 3; s++) {
        const uint32_t db = sb_u + s * 40960 + soff;
        const int kk = s * 32;
        CP16(db, srcAh + kk);
        CP16(db + 10240, srcAl + kk);
        CP16(db + 20480, srcBh + kk);
        CP16(db + 30720, srcBl + kk);
        CP_COMMIT();
    }

    for (int kt = 0; kt < NK; kt++) {
        CP_WAIT(2);
        __syncthreads();
        if (kt + 3 < NK) {
            const uint32_t db = sb_u + ((kt + 3) & 3) * 40960 + soff;
            const int kk = (kt + 3) * 32;
            CP16(db, srcAh + kk);
            CP16(db + 10240, srcAl + kk);
            CP16(db + 20480, srcBh + kk);
            CP16(db + 30720, srcBl + kk);
        }
        CP_COMMIT();

        const uint32_t base_u = sb_u + (kt & 3) * 40960;
#pragma unroll
        for (int ks = 0; ks < 2; ks++) {
            const uint32_t ko = ks * 32;
            uint32_t ah[2][4], al[2][4], bh[2][4], bl[2][4];
#pragma unroll
            for (int i = 0; i < 2; i++) {
                LDSM4(ah[i], base_u + a_fa + i * 1280 + ko);
                LDSM4(al[i], base_u + 10240 + a_fa + i * 1280 + ko);
            }
#pragma unroll
            for (int jp = 0; jp < 2; jp++) {
                LDSM4(bh[jp], base_u + 20480 + b_fa + jp * 1280 + ko);
                LDSM4(bl[jp], base_u + 30720 + b_fa + jp * 1280 + ko);
            }
#pragma unroll
            for (int j = 0; j < 4; j++) {
                const int jp = j >> 1, sel = j & 1;
                uint32_t b0h = bh[jp][sel], b1h = bh[jp][2 + sel];
                uint32_t b0l = bl[jp][sel], b1l = bl[jp][2 + sel];
#pragma unroll
                for (int i = 0; i < 2; i++) {
                    mma16(acc[i][j], ah[i][0], ah[i][1], ah[i][2], ah[i][3], b0h, b1h);
                    mma16(acc[i][j], ah[i][0], ah[i][1], ah[i][2], ah[i][3], b0l, b1l);
                    mma16(acc[i][j], al[i][0], al[i][1], al[i][2], al[i][3], b0h, b1h);
                }
            }
        }
    }

    // Epilogue
#pragma unroll
    for (int i = 0; i < 2; i++) {
        int row = m0 + wm + i * 16 + r4;
#pragma unroll
        for (int j = 0; j < 4; j++) {
            int col = n0 + wn + j * 8 + kp * 2;
            float b0 = bias[col], b1 = bias[col + 1];
            float v00 = acc[i][j][0] + b0, v01 = acc[i][j][1] + b1;
            float v10 = acc[i][j][2] + b0, v11 = acc[i][j][3] + b1;
            if (MODE == 0) {
                qkv_store_bf(row, col, v00, v01);
                qkv_store_bf(row + 8, col, v10, v11);
            } else {
                *reinterpret_cast<float2*>(out + (size_t)row * NTOT + col) = make_float2(v00, v01);
                *reinterpret_cast<float2*>(out + (size_t)(row + 8) * NTOT + col) = make_float2(v10, v11);
            }
        }
    }
}

// ---------------------------------------------------------------------------
// Flash attention, causal, bf16 3-term, pre-split bf16 Q/K/V inputs,
// cp.async 3-stage K/V ring, ldmatrix (V via .trans from row-major), P in regs.
// Q-tile 128, key-tile 64, 8 warps x 16 q-rows. Rows padded to 72 bf16 (144B).
// smem: Qh/Ql [128][72] + 3 stages x {Kh,Kl,Vh,Vl}[64][72] = 147456 B.
// ---------------------------------------------------------------------------
#define ATT_SMEM_BYTES 147456

__global__ __launch_bounds__(256, 1) void attn_kernel() {
    extern __shared__ __nv_bfloat16 sb[];
    const uint32_t sb_u = smem_to_u32(sb);

    const int tid = threadIdx.x, lane = tid & 31, warp = tid >> 5;
    const int kp = lane & 3, r4 = lane >> 2;
    const int l16 = lane & 15, lhi = lane >> 4;
    const int bh_idx = blockIdx.y;
    const int q0 = blockIdx.x * 128;
    const __nv_bfloat16* Qh_g = g_qh + (size_t)bh_idx * T_SEQ * HD;
    const __nv_bfloat16* Ql_g = g_ql + (size_t)bh_idx * T_SEQ * HD;
    const __nv_bfloat16* Kh_g = g_kh + (size_t)bh_idx * T_SEQ * HD;
    const __nv_bfloat16* Kl_g = g_kl + (size_t)bh_idx * T_SEQ * HD;
    const __nv_bfloat16* Vh_g = g_vh + (size_t)bh_idx * T_SEQ * HD;
    const __nv_bfloat16* Vl_g = g_vl + (size_t)bh_idx * T_SEQ * HD;

    // staging coords: K/V tile 64 rows x 64 bf16 (8 chunks of 16B)
    const int krow = tid >> 2, kch = tid & 3;   // chunks kch and kch+4
    const uint32_t kvoff = (uint32_t)krow * 144 + (uint32_t)kch * 16;

    const int ntiles = (q0 >> 6) + 2;

    // --- prologue: Q (group 0, with stage 0) + stage 1 ---
    {
        // Q: 128 rows x 8 chunks, h and l
#pragma unroll
        for (int i = 0; i < 4; i++) {
            int unit = tid + i * 256;
            int row = unit >> 3, c = unit & 7;
            uint32_t d = (uint32_t)row * 144 + (uint32_t)c * 16;
            CP16(sb_u + d, Qh_g + (size_t)(q0 + row) * HD + c * 8);
            CP16(sb_u + 18432 + d, Ql_g + (size_t)(q0 + row) * HD + c * 8);
        }
        // stage 0 K/V
        const uint32_t base = sb_u + 36864;
        CP16(base + kvoff, Kh_g + (size_t)krow * HD + kch * 8);
        CP16(base + kvoff + 64, Kh_g + (size_t)krow * HD + kch * 8 + 32);
        CP16(base + 9216 + kvoff, Kl_g + (size_t)krow * HD + kch * 8);
        CP16(base + 9216 + kvoff + 64, Kl_g + (size_t)krow * HD + kch * 8 + 32);
        CP16(base + 18432 + kvoff, Vh_g + (size_t)krow * HD + kch * 8);
        CP16(base + 18432 + kvoff + 64, Vh_g + (size_t)krow * HD + kch * 8 + 32);
        CP16(base + 27648 + kvoff, Vl_g + (size_t)krow * HD + kch * 8);
        CP16(base + 27648 + kvoff + 64, Vl_g + (size_t)krow * HD + kch * 8 + 32);
        CP_COMMIT();
        // stage 1 K/V (always valid: ntiles >= 2)
        const uint32_t base1 = sb_u + 36864 + 36864;
        const size_t r1 = (size_t)(64 + krow) * HD + kch * 8;
        CP16(base1 + kvoff, Kh_g + r1);
        CP16(base1 + kvoff + 64, Kh_g + r1 + 32);
        CP16(base1 + 9216 + kvoff, Kl_g + r1);
        CP16(base1 + 9216 + kvoff + 64, Kl_g + r1 + 32);
        CP16(base1 + 18432 + kvoff, Vh_g + r1);
        CP16(base1 + 18432 + kvoff + 64, Vh_g + r1 + 32);
        CP16(base1 + 27648 + kvoff, Vl_g + r1);
        CP16(base1 + 27648 + kvoff + 64, Vl_g + r1 + 32);
        CP_COMMIT();
    }

    // ldmatrix bases
    const uint32_t qbaseH = sb_u + (uint32_t)(warp * 16 + l16) * 144 + lhi * 16;
    const uint32_t qbaseL = qbaseH + 18432;
    const uint32_t frag_kv = (uint32_t)l16 * 144 + lhi * 16;

    float o[8][4];
#pragma unroll
    for (int j = 0; j < 8; j++)
#pragma unroll
        for (int r = 0; r < 4; r++) o[j][r] = 0.f;
    float mA = -1e30f, mB = -1e30f, lA = 0.f, lB = 0.f;

    const int rA = q0 + warp * 16 + r4;
    const int rB = rA + 8;

    for (int kt = 0; kt < ntiles; kt++) {
        const int kt0 = kt << 6;
        CP_WAIT(1);
        __syncthreads();
        if (kt + 2 < ntiles) {
            const uint32_t base = sb_u + 36864 + ((kt + 2) % 3) * 36864;
            const size_t rs = (size_t)(kt0 + 128 + krow) * HD + kch * 8;
            CP16(base + kvoff, Kh_g + rs);
            CP16(base + kvoff + 64, Kh_g + rs + 32);
            CP16(base + 9216 + kvoff, Kl_g + rs);
            CP16(base + 9216 + kvoff + 64, Kl_g + rs + 32);
            CP16(base + 18432 + kvoff, Vh_g + rs);
            CP16(base + 18432 + kvoff + 64, Vh_g + rs + 32);
            CP16(base + 27648 + kvoff, Vl_g + rs);
            CP16(base + 27648 + kvoff + 64, Vl_g + rs + 32);
        }
        CP_COMMIT();

        const uint32_t stb = sb_u + 36864 + (kt % 3) * 36864;
        const uint32_t kbufH = stb + frag_kv;
        const uint32_t kbufL = stb + 9216 + frag_kv;
        const uint32_t vbufH = stb + 18432 + frag_kv;
        const uint32_t vbufL = stb + 27648 + frag_kv;

        // S = Q * K^T
        float s[8][4];
#pragma unroll
        for (int j = 0; j < 8; j++)
#pragma unroll
            for (int r = 0; r < 4; r++) s[j][r] = 0.f;

#pragma unroll
        for (int ks = 0; ks < 4; ks++) {
            const uint32_t ko = ks * 32;
            uint32_t qh[4], ql[4], kh[4][4], kl[4][4];
            LDSM4(qh, qbaseH + ko);
            LDSM4(ql, qbaseL + ko);
#pragma unroll
            for (int jp = 0; jp < 4; jp++) {
                LDSM4(kh[jp], kbufH + jp * 2304 + ko);
                LDSM4(kl[jp], kbufL + jp * 2304 + ko);
            }
#pragma unroll
            for (int j = 0; j < 8; j++) {
                const int jp = j >> 1, sel = j & 1;
                uint32_t b0h = kh[jp][sel], b1h = kh[jp][2 + sel];
                uint32_t b0l = kl[jp][sel], b1l = kl[jp][2 + sel];
                mma16(s[j], qh[0], qh[1], qh[2], qh[3], b0h, b1h);
                mma16(s[j], qh[0], qh[1], qh[2], qh[3], b0l, b1l);
                mma16(s[j], ql[0], ql[1], ql[2], ql[3], b0h, b1h);
            }
        }

        // Causal mask (diagonal-band tiles only)
        if (kt0 + 63 > q0) {
#pragma unroll
            for (int j = 0; j < 8; j++) {
                int c = kt0 + j * 8 + kp * 2;
                if (c > rA) s[j][0] = -1e30f;
                if (c + 1 > rA) s[j][1] = -1e30f;
                if (c > rB) s[j][2] = -1e30f;
                if (c + 1 > rB) s[j][3] = -1e30f;
            }
        }

        // Online softmax
        float tA = -1e30f, tB = -1e30f;
#pragma unroll
        for (int j = 0; j < 8; j++) {
            tA = fmaxf(tA, fmaxf(s[j][0], s[j][1]));
            tB = fmaxf(tB, fmaxf(s[j][2], s[j][3]));
        }
        tA = fmaxf(tA, __shfl_xor_sync(0xffffffffu, tA, 1));
        tA = fmaxf(tA, __shfl_xor_sync(0xffffffffu, tA, 2));
        tB = fmaxf(tB, __shfl_xor_sync(0xffffffffu, tB, 1));
        tB = fmaxf(tB, __shfl_xor_sync(0xffffffffu, tB, 2));
        float mAn = fmaxf(mA, tA), mBn = fmaxf(mB, tB);
        float aA = __expf(mA - mAn), aB = __expf(mB - mBn);
        mA = mAn; mB = mBn;
        lA *= aA; lB *= aB;

        // P in registers (C-fragment layout == A-fragment layout)
        uint32_t ph01[8], ph23[8], pl01[8], pl23[8];
#pragma unroll
        for (int j = 0; j < 8; j++) {
            float p0 = __expf(s[j][0] - mA), p1 = __expf(s[j][1] - mA);
            float p2 = __expf(s[j][2] - mB), p3 = __expf(s[j][3] - mB);
            lA += p0 + p1;
            lB += p2 + p3;
            o[j][0] *= aA; o[j][1] *= aA; o[j][2] *= aB; o[j][3] *= aB;
            bsplit2(p0, p1, ph01[j], pl01[j]);
            bsplit2(p2, p3, ph23[j], pl23[j]);
        }

        // O += P * V  (V row-major [key][d], fragments via ldmatrix.trans)
#pragma unroll
        for (int ks = 0; ks < 4; ks++) {
            uint32_t ah0 = ph01[2 * ks],     ah1 = ph23[2 * ks];
            uint32_t ah2 = ph01[2 * ks + 1], ah3 = ph23[2 * ks + 1];
            uint32_t al0 = pl01[2 * ks],     al1 = pl23[2 * ks];
            uint32_t al2 = pl01[2 * ks + 1], al3 = pl23[2 * ks + 1];
            uint32_t vh[4][4], vl[4][4];
#pragma unroll
            for (int jp = 0; jp < 4; jp++) {
                LDSM4T(vh[jp], vbufH + ks * 2304 + jp * 32);
                LDSM4T(vl[jp], vbufL + ks * 2304 + jp * 32);
            }
#pragma unroll
            for (int j = 0; j < 8; j++) {
                const int jp = j >> 1, sel = j & 1;
                uint32_t v0h = vh[jp][2 * sel], v1h = vh[jp][2 * sel + 1];
                uint32_t v0l = vl[jp][2 * sel], v1l = vl[jp][2 * sel + 1];
                mma16(o[j], ah0, ah1, ah2, ah3, v0h, v1h);
                mma16(o[j], ah0, ah1, ah2, ah3, v0l, v1l);
                mma16(o[j], al0, al1, al2, al3, v0h, v1h);
            }
        }
    }

    // Normalize and write pre-split bf16 Y
    lA += __shfl_xor_sync(0xffffffffu, lA, 1);
    lA += __shfl_xor_sync(0xffffffffu, lA, 2);
    lB += __shfl_xor_sync(0xffffffffu, lB, 1);
    lB += __shfl_xor_sync(0xffffffffu, lB, 2);
    float iA = 1.f / lA, iB = 1.f / lB;

    const int b = bh_idx >> 4, h = bh_idx & 15;
    const int tokA = b * T_SEQ + rA;
#pragma unroll
    for (int j = 0; j < 8; j++) {
        int col = h * 64 + j * 8 + kp * 2;
        size_t oA = (size_t)tokA * CDIM + col;
        size_t oB = (size_t)(tokA + 8) * CDIM + col;
        uint32_t hp, lp;
        bsplit2(o[j][0] * iA, o[j][1] * iA, hp, lp);
        *reinterpret_cast<uint32_t*>(g_yh + oA) = hp;
        *reinterpret_cast<uint32_t*>(g_yl + oA) = lp;
        bsplit2(o[j][2] * iB, o[j][3] * iB, hp, lp);
        *reinterpret_cast<uint32_t*>(g_yh + oB) = hp;
        *reinterpret_cast<uint32_t*>(g_yl + oB) = lp;
    }
}

// ---------------- launch ----------------
extern "C" void kernel_launch(void* const* d_in, const int* in_sizes, int n_in,
                              void* d_out, int out_size) {
    const float* x    = (const float*)d_in[0];
    const float* Wqkv = (const float*)d_in[1];
    const float* bqkv = (const float*)d_in[2];
    const float* Wp   = (const float*)d_in[3];
    const float* bp   = (const float*)d_in[4];
    float* out = (float*)d_out;

    void *xh, *xl, *wh, *wl, *wph, *wpl, *yh, *yl;
    cudaGetSymbolAddress(&xh, g_xh);   cudaGetSymbolAddress(&xl, g_xl);
    cudaGetSymbolAddress(&wh, g_wh);   cudaGetSymbolAddress(&wl, g_wl);
    cudaGetSymbolAddress(&wph, g_wph); cudaGetSymbolAddress(&wpl, g_wpl);
    cudaGetSymbolAddress(&yh, g_yh);   cudaGetSymbolAddress(&yl, g_yl);

    cudaFuncSetAttribute(attn_kernel, cudaFuncAttributeMaxDynamicSharedMemorySize,
                         ATT_SMEM_BYTES);
    cudaFuncSetAttribute(gemm_bf16<3 * CDIM, 0>, cudaFuncAttributeMaxDynamicSharedMemorySize,
                         GEMM_SMEM_BYTES);
    cudaFuncSetAttribute(gemm_bf16<CDIM, 1>, cudaFuncAttributeMaxDynamicSharedMemorySize,
                         GEMM_SMEM_BYTES);

    // 0) pre-split inputs/weights
    xsplit_kernel<<<(MROWS * CDIM / 4) / 256, 256>>>(x, (__nv_bfloat16*)xh, (__nv_bfloat16*)xl);
    wsplit_kernel<<<dim3(3 * CDIM / 32, CDIM / 32), dim3(32, 8)>>>(
        Wqkv, (__nv_bfloat16*)wh, (__nv_bfloat16*)wl, 3 * CDIM);
    wsplit_kernel<<<dim3(CDIM / 32, CDIM / 32), dim3(32, 8)>>>(
        Wp, (__nv_bfloat16*)wph, (__nv_bfloat16*)wpl, CDIM);

    // 1) QKV projection -> pre-split bf16 g_q*/g_k*/g_v*
    gemm_bf16<3 * CDIM, 0><<<dim3(MROWS / 128, 3 * CDIM / 128), 512, GEMM_SMEM_BYTES>>>(
        (const __nv_bfloat16*)xh, (const __nv_bfloat16*)xl,
        (const __nv_bfloat16*)wh, (const __nv_bfloat16*)wl, bqkv, nullptr);

    // 2) causal flash attention -> g_yh/g_yl (pre-split)
    attn_kernel<<<dim3(T_SEQ / 128, BSZ * NHEAD), 256, ATT_SMEM_BYTES>>>();

    // 3) output projection -> d_out
    gemm_bf16<CDIM, 1><<<dim3(MROWS / 128, CDIM / 128), 512, GEMM_SMEM_BYTES>>>(
        (const __nv_bfloat16*)yh, (const __nv_bfloat16*)yl,
        (const __nv_bfloat16*)wph, (const __nv_bfloat16*)wpl, bp, out);
}